// round 2
// baseline (speedup 1.0000x reference)
#include <cuda_runtime.h>
#include <math.h>
#include <stdint.h>

#define BB   4
#define NN   16384
#define CIN  128
#define COUT 256
#define HH   256
#define WW   256
#define NP   65536      // N0 = H*W points
#define HD   128
#define WD   128
#define HC   64
#define WC   64
#define NS   4096       // HC*WC
#define EPSV 1e-6f

// ---------------- scratch (device globals: no allocation allowed) ----------------
__device__ float  g_ssum[(size_t)BB*HH*WW*CIN];   // token2map sum -> normalized map (128MB)
__device__ float  g_cnt [(size_t)BB*HH*WW];       // token2map count
__device__ float  g_y   [(size_t)BB*HD*WD*COUT];  // conv output        (64MB)
__device__ float  g_num [(size_t)BB*NN*COUT];     // map2token num -> tok (64MB)
__device__ float  g_den [(size_t)BB*NN];
__device__ float  g_tokn[(size_t)BB*NN*COUT];     // BN-normalized tokens (64MB)
__device__ float  g_wexp[(size_t)BB*NN];          // exp(conf)
__device__ double g_bnsum[COUT];
__device__ double g_bnsq [COUT];
__device__ float  g_scale[COUT];
__device__ float  g_shift[COUT];
__device__ float  g_cnum[(size_t)BB*NS*COUT];     // cluster num (16MB)
__device__ float  g_cden[(size_t)BB*NS];
__device__ float  g_wpt [(size_t)BB*NP];          // per-point weight, reused
__device__ unsigned g_maxw[BB];
__device__ float  g_wT  [CIN*COUT];               // skip_w transposed [k][n]

// ---------------- helpers ----------------
__device__ __forceinline__ void red_add4(float* p, float4 v) {
    asm volatile("red.global.add.v4.f32 [%0], {%1,%2,%3,%4};"
                 :: "l"(__cvta_generic_to_global(p)),
                    "f"(v.x), "f"(v.y), "f"(v.z), "f"(v.w) : "memory");
}

__device__ __forceinline__ int grid_cell(float lx, float ly, int Hg, int Wg) {
    lx = fminf(fmaxf(lx, -1.f), 1.f);
    ly = fminf(fmaxf(ly, -1.f), 1.f);
    int px = min(max(__float2int_rn(0.5f*(lx+1.f)*(float)Wg - 0.5f), 0), Wg-1);
    int py = min(max(__float2int_rn(0.5f*(ly+1.f)*(float)Hg - 0.5f), 0), Hg-1);
    return py*Wg + px;
}

__device__ __forceinline__ float to_tf32(float x) {
    uint32_t u; asm("cvt.rna.tf32.f32 %0, %1;" : "=r"(u) : "f"(x));
    return __uint_as_float(u);
}

__device__ __forceinline__ void mma8(float& d0, float& d1, float& d2, float& d3,
                                     uint32_t a0, uint32_t a1, uint32_t a2, uint32_t a3,
                                     uint32_t b0, uint32_t b1) {
    asm volatile("mma.sync.aligned.m16n8k8.row.col.f32.tf32.tf32.f32 "
                 "{%0,%1,%2,%3},{%4,%5,%6,%7},{%8,%9},{%0,%1,%2,%3};"
                 : "+f"(d0), "+f"(d1), "+f"(d2), "+f"(d3)
                 : "r"(a0), "r"(a1), "r"(a2), "r"(a3), "r"(b0), "r"(b1));
}

// ---------------- kernels ----------------
__global__ void k_zero() {
    size_t t = (size_t)blockIdx.x*blockDim.x + threadIdx.x;
    size_t stride = (size_t)gridDim.x*blockDim.x;
    float4 z = make_float4(0.f,0.f,0.f,0.f);
    for (size_t i=t; i < (size_t)BB*HH*WW*CIN/4; i+=stride) ((float4*)g_ssum)[i]=z;
    for (size_t i=t; i < (size_t)BB*HH*WW/4;     i+=stride) ((float4*)g_cnt )[i]=z;
    for (size_t i=t; i < (size_t)BB*NN*COUT/4;   i+=stride) ((float4*)g_num )[i]=z;
    for (size_t i=t; i < (size_t)BB*NN/4;        i+=stride) ((float4*)g_den )[i]=z;
    for (size_t i=t; i < (size_t)BB*NS*COUT/4;   i+=stride) ((float4*)g_cnum)[i]=z;
    for (size_t i=t; i < (size_t)BB*NS/4;        i+=stride) ((float4*)g_cden)[i]=z;
    if (t < COUT) { g_bnsum[t]=0.0; g_bnsq[t]=0.0; }
    if (t < BB)   g_maxw[t]=0u;
}

// scatter token features to H x W map (sum + count)
__global__ void k_token2map(const float* __restrict__ x, const float* __restrict__ loc,
                            const int* __restrict__ idx_agg) {
    int p    = blockIdx.x*8 + (threadIdx.x>>5);
    int lane = threadIdx.x & 31;
    int b    = p >> 16;
    float lx = loc[2*p], ly = loc[2*p+1];
    int cell = grid_cell(lx, ly, HH, WW);
    int i    = idx_agg[p];
    const float4* src = (const float4*)(x + ((size_t)b*NN + i)*CIN);
    float* dst = g_ssum + ((size_t)b*HH*WW + cell)*CIN;
    float4 v = src[lane];
    red_add4(dst + lane*4, v);
    if (!lane) atomicAdd(&g_cnt[(size_t)b*HH*WW + cell], 1.0f);
}

// normalize map in place: ssum /= (cnt + eps)
__global__ void k_norm() {
    size_t i = (size_t)blockIdx.x*256 + threadIdx.x;      // over BB*HH*WW*CIN/4 float4s
    float rcp = 1.f/(g_cnt[i >> 5] + EPSV);
    float4 v = ((float4*)g_ssum)[i];
    v.x*=rcp; v.y*=rcp; v.z*=rcp; v.w*=rcp;
    ((float4*)g_ssum)[i] = v;
}

__global__ void k_transpose(const float* __restrict__ w) { // w[COUT][CIN] -> g_wT[CIN][COUT]
    int t = blockIdx.x*blockDim.x + threadIdx.x;
    g_wT[t] = w[(t % COUT)*CIN + (t / COUT)];
}

// ---- 3x3 stride-2 conv as implicit GEMM on TF32 tensor cores ----
// block: one output row (oy), one N-half (128 couts). M=128 pixels, K=1152 (72 x K16).
__global__ void __launch_bounds__(256) k_conv(const float* __restrict__ cw,
                                              const float* __restrict__ cb) {
    __shared__ float4 As[2][8][2][8][4];   // [buf][mtile][k8chunk][g][c'] 16KB
    __shared__ float4 Bs[2][16][8][4];     // [buf][ntile][n_in_tile][c]  16KB
    int oy = blockIdx.x, nh = blockIdx.y, b = blockIdx.z;
    int n0 = nh*128;
    int tid = threadIdx.x;

    // staging ids (A): pixel = ox, k8 chunk
    int sp  = tid & 127;
    int sch = tid >> 7;
    int smt = sp >> 4, sr = sp & 15, sg = sr & 7, shf = sr >> 3;
    int ssw = (sg >> 1) & 3;

    // compute ids
    int w = tid >> 5, lane = tid & 31;
    int wm = w & 3, wn = w >> 2;           // warp tile: m-tiles {2wm,2wm+1}, n base 64*wn
    int g = lane >> 2, c = lane & 3;
    int csw = c ^ ((g >> 1) & 3);

    float acc[2][8][4];
    #pragma unroll
    for (int i=0;i<2;i++) for (int t=0;t<8;t++) for (int r=0;r<4;r++) acc[i][t][r]=0.f;

    const float* xin = g_ssum + (size_t)b*HH*WW*CIN;

    float4 nlo, nhi;            // A staging regs
    float  nb[8];               // B staging regs (2 iters x 4)
    int    bnt[2], bbg[2], bbc[2];
    {
        #pragma unroll
        for (int it=0; it<2; it++) {
            int idx = tid + 256*it;
            bnt[it] = idx >> 5; bbg[it] = (idx >> 2) & 7; bbc[it] = idx & 3;
        }
    }

    // ---- prologue: stage kk=0 ----
    {
        int tap = 0, cinb = 0;
        int iy = 2*oy - 1;            // ky=0
        int ix = 2*sp - 1;            // kx=0
        bool ok = (iy >= 0) && (ix >= 0);
        nlo = make_float4(0,0,0,0); nhi = nlo;
        if (ok) {
            const float4* ap = (const float4*)(xin + ((size_t)iy*WW + ix)*CIN + cinb + sch*8);
            nlo = ap[0]; nhi = ap[1];
        }
        #pragma unroll
        for (int it=0; it<2; it++) {
            const float* bp = cw + (size_t)(tap*CIN + cinb + bbc[it])*COUT + n0 + bnt[it]*8 + bbg[it];
            nb[it*4+0]=bp[0]; nb[it*4+1]=bp[4*COUT]; nb[it*4+2]=bp[8*COUT]; nb[it*4+3]=bp[12*COUT];
        }
        // cvt + STS into buf 0
        float la[4], ha[4];
        *(float4*)la = nlo; *(float4*)ha = nhi;
        float2* ab = (float2*)&As[0][smt][sch][0][0];
        #pragma unroll
        for (int c4=0;c4<4;c4++) {
            int idx = sg*4 + (c4 ^ ssw);
            ab[idx*2+shf] = make_float2(to_tf32(la[c4]), to_tf32(ha[c4]));
        }
        #pragma unroll
        for (int it=0; it<2; it++)
            Bs[0][bnt[it]][bbg[it]][bbc[it]] =
                make_float4(to_tf32(nb[it*4+0]), to_tf32(nb[it*4+1]),
                            to_tf32(nb[it*4+2]), to_tf32(nb[it*4+3]));
    }
    __syncthreads();

    for (int kk = 0; kk < 72; kk++) {
        int buf = kk & 1;
        // ---- prefetch kk+1 into regs ----
        if (kk < 71) {
            int k2 = kk + 1;
            int tap = k2 >> 3, cinb = (k2 & 7) << 4;
            int ky = tap/3, kx = tap - 3*ky;
            int iy = 2*oy - 1 + ky;
            int ix = 2*sp - 1 + kx;
            bool ok = (iy >= 0) && (ix >= 0);
            nlo = make_float4(0,0,0,0); nhi = nlo;
            if (ok) {
                const float4* ap = (const float4*)(xin + ((size_t)iy*WW + ix)*CIN + cinb + sch*8);
                nlo = ap[0]; nhi = ap[1];
            }
            #pragma unroll
            for (int it=0; it<2; it++) {
                const float* bp = cw + (size_t)(tap*CIN + cinb + bbc[it])*COUT + n0 + bnt[it]*8 + bbg[it];
                nb[it*4+0]=bp[0]; nb[it*4+1]=bp[4*COUT]; nb[it*4+2]=bp[8*COUT]; nb[it*4+3]=bp[12*COUT];
            }
        }
        // ---- compute on buf ----
        float4 afr[2][2];
        #pragma unroll
        for (int i=0;i<2;i++) {
            afr[i][0] = As[buf][2*wm+i][0][g][csw];
            afr[i][1] = As[buf][2*wm+i][1][g][csw];
        }
        #pragma unroll
        for (int t=0;t<8;t++) {
            float4 bv = Bs[buf][wn*8+t][g][c];
            #pragma unroll
            for (int i=0;i<2;i++) {
                mma8(acc[i][t][0], acc[i][t][1], acc[i][t][2], acc[i][t][3],
                     __float_as_uint(afr[i][0].x), __float_as_uint(afr[i][0].z),
                     __float_as_uint(afr[i][0].y), __float_as_uint(afr[i][0].w),
                     __float_as_uint(bv.x), __float_as_uint(bv.y));
                mma8(acc[i][t][0], acc[i][t][1], acc[i][t][2], acc[i][t][3],
                     __float_as_uint(afr[i][1].x), __float_as_uint(afr[i][1].z),
                     __float_as_uint(afr[i][1].y), __float_as_uint(afr[i][1].w),
                     __float_as_uint(bv.z), __float_as_uint(bv.w));
            }
        }
        // ---- store staged regs into other buffer ----
        if (kk < 71) {
            int ob = buf ^ 1;
            float la[4], ha[4];
            *(float4*)la = nlo; *(float4*)ha = nhi;
            float2* ab = (float2*)&As[ob][smt][sch][0][0];
            #pragma unroll
            for (int c4=0;c4<4;c4++) {
                int idx = sg*4 + (c4 ^ ssw);
                ab[idx*2+shf] = make_float2(to_tf32(la[c4]), to_tf32(ha[c4]));
            }
            #pragma unroll
            for (int it=0; it<2; it++)
                Bs[ob][bnt[it]][bbg[it]][bbc[it]] =
                    make_float4(to_tf32(nb[it*4+0]), to_tf32(nb[it*4+1]),
                                to_tf32(nb[it*4+2]), to_tf32(nb[it*4+3]));
        }
        __syncthreads();
    }

    // ---- epilogue: bias + store ----
    #pragma unroll
    for (int i=0;i<2;i++) {
        int ox = (2*wm + i)*16 + g;
        float* yrow0 = g_y + (((size_t)b*HD + oy)*WD + ox)*COUT;
        float* yrow1 = yrow0 + 8*COUT;               // ox + 8
        #pragma unroll
        for (int t=0;t<8;t++) {
            int n = n0 + wn*64 + t*8 + 2*c;
            float b0 = cb[n], b1 = cb[n+1];
            *(float2*)(yrow0 + n) = make_float2(acc[i][t][0]+b0, acc[i][t][1]+b1);
            *(float2*)(yrow1 + n) = make_float2(acc[i][t][2]+b0, acc[i][t][3]+b1);
        }
    }
}

// bilinear gather from conv map at orig points, weighted scatter to tokens
__global__ void k_map2token(const float* __restrict__ loc, const int* __restrict__ idx_agg,
                            const float* __restrict__ aggw) {
    int p    = blockIdx.x*8 + (threadIdx.x>>5);
    int lane = threadIdx.x & 31;
    int b    = p >> 16;
    float lx = fminf(fmaxf(loc[2*p],   -1.f), 1.f);
    float ly = fminf(fmaxf(loc[2*p+1], -1.f), 1.f);
    float fx = fminf(fmaxf(0.5f*(lx+1.f)*(float)WD - 0.5f, 0.f), (float)(WD-1));
    float fy = fminf(fmaxf(0.5f*(ly+1.f)*(float)HD - 0.5f, 0.f), (float)(HD-1));
    float x0f = floorf(fx), y0f = floorf(fy);
    float wx = fx - x0f, wy = fy - y0f;
    int x0 = (int)x0f, y0 = (int)y0f;
    int x1 = min(x0+1, WD-1), y1 = min(y0+1, HD-1);
    const float* base = g_y + (size_t)b*HD*WD*COUT;
    const float4* r00 = (const float4*)(base + (size_t)(y0*WD+x0)*COUT);
    const float4* r01 = (const float4*)(base + (size_t)(y0*WD+x1)*COUT);
    const float4* r10 = (const float4*)(base + (size_t)(y1*WD+x0)*COUT);
    const float4* r11 = (const float4*)(base + (size_t)(y1*WD+x1)*COUT);
    float w00=(1.f-wx)*(1.f-wy), w01=wx*(1.f-wy), w10=(1.f-wx)*wy, w11=wx*wy;
    float wpt = aggw[p];
    int i = idx_agg[p];
    float* dst = g_num + ((size_t)b*NN + i)*COUT;
    #pragma unroll
    for (int q = 0; q < 2; q++) {
        int c4 = q*32 + lane;
        float4 a = r00[c4], bq = r01[c4], cc = r10[c4], d = r11[c4];
        float4 f;
        f.x = (w00*a.x + w01*bq.x + w10*cc.x + w11*d.x)*wpt;
        f.y = (w00*a.y + w01*bq.y + w10*cc.y + w11*d.y)*wpt;
        f.z = (w00*a.z + w01*bq.z + w10*cc.z + w11*d.z)*wpt;
        f.w = (w00*a.w + w01*bq.w + w10*cc.w + w11*d.w)*wpt;
        red_add4(dst + c4*4, f);
    }
    if (!lane) atomicAdd(&g_den[(size_t)b*NN + i], wpt);
}

// skip GEMM (x @ skip_w^T) fused with tok = num/(den+eps) + skip -> overwrite g_num
__global__ void __launch_bounds__(256) k_skip(const float* __restrict__ x) {
    __shared__ __align__(16) float As2[16][68];
    __shared__ __align__(16) float Bs2[16][64];
    int m0 = blockIdx.x*64, n0 = blockIdx.y*64;
    int tid = threadIdx.x;
    int tx = tid & 15, ty = tid >> 4;
    int m_l = tid >> 2, kq = (tid & 3)*4;
    int kb  = tid >> 4, nb = (tid & 15)*4;
    float acc[4][4] = {};
    const float* arow = x + (size_t)(m0 + m_l)*CIN;
    for (int cc = 0; cc < 8; cc++) {
        float4 va = *(const float4*)(arow + cc*16 + kq);
        __syncthreads();
        As2[kq+0][m_l]=va.x; As2[kq+1][m_l]=va.y; As2[kq+2][m_l]=va.z; As2[kq+3][m_l]=va.w;
        *(float4*)&Bs2[kb][nb] = *(const float4*)(g_wT + (size_t)(cc*16+kb)*COUT + n0 + nb);
        __syncthreads();
        #pragma unroll
        for (int k = 0; k < 16; k++) {
            float4 a  = *(float4*)&As2[k][ty*4];
            float4 bv = *(float4*)&Bs2[k][tx*4];
            acc[0][0]+=a.x*bv.x; acc[0][1]+=a.x*bv.y; acc[0][2]+=a.x*bv.z; acc[0][3]+=a.x*bv.w;
            acc[1][0]+=a.y*bv.x; acc[1][1]+=a.y*bv.y; acc[1][2]+=a.y*bv.z; acc[1][3]+=a.y*bv.w;
            acc[2][0]+=a.z*bv.x; acc[2][1]+=a.z*bv.y; acc[2][2]+=a.z*bv.z; acc[2][3]+=a.z*bv.w;
            acc[3][0]+=a.w*bv.x; acc[3][1]+=a.w*bv.y; acc[3][2]+=a.w*bv.z; acc[3][3]+=a.w*bv.w;
        }
    }
    #pragma unroll
    for (int i2 = 0; i2 < 4; i2++) {
        int row = m0 + ty*4 + i2;
        float rcp = 1.f/(g_den[row] + EPSV);
        float* orow = g_num + (size_t)row*COUT + n0 + tx*4;
        float4 nv = *(float4*)orow;
        float4 o = make_float4(acc[i2][0] + nv.x*rcp, acc[i2][1] + nv.y*rcp,
                               acc[i2][2] + nv.z*rcp, acc[i2][3] + nv.w*rcp);
        *(float4*)orow = o;
    }
}

__global__ void k_bnstats() {
    int c  = threadIdx.x;
    int r0 = blockIdx.x*256;
    double s = 0.0, s2 = 0.0;
    for (int r = 0; r < 256; r++) {
        float v = g_num[(size_t)(r0 + r)*COUT + c];
        s += v; s2 += (double)v*v;
    }
    atomicAdd(&g_bnsum[c], s);
    atomicAdd(&g_bnsq[c],  s2);
}

__global__ void k_bnfinal(const float* __restrict__ gam, const float* __restrict__ bet) {
    int c = threadIdx.x;
    double m  = (double)BB*NN;
    double mu = g_bnsum[c]/m;
    double var = g_bnsq[c]/m - mu*mu;
    float sc = gam[c] * (float)(1.0/sqrt(var + 1e-5));
    g_scale[c] = sc;
    g_shift[c] = bet[c] - (float)mu*sc;
}

__global__ void k_bnconf(const float* __restrict__ cw, const float* __restrict__ cbv,
                         float* __restrict__ out_xout, float* __restrict__ out_conf) {
    int row  = blockIdx.x*8 + (threadIdx.x>>5);
    int lane = threadIdx.x & 31;
    const float4* t  = (const float4*)(g_num  + (size_t)row*COUT);
    float4* tn       = (float4*)(g_tokn + (size_t)row*COUT);
    float4* xo       = (float4*)(out_xout + (size_t)row*COUT);
    float dot = 0.f;
    #pragma unroll
    for (int q = 0; q < 2; q++) {
        int c4 = q*32 + lane;
        float4 v  = t[c4];
        float4 sc = ((const float4*)g_scale)[c4];
        float4 sh = ((const float4*)g_shift)[c4];
        float4 w  = ((const float4*)cw)[c4];
        float4 r = make_float4(v.x*sc.x+sh.x, v.y*sc.y+sh.y, v.z*sc.z+sh.z, v.w*sc.w+sh.w);
        dot += r.x*w.x + r.y*w.y + r.z*w.z + r.w*w.w;
        tn[c4] = r;
        xo[c4] = make_float4(fmaxf(r.x,0.f), fmaxf(r.y,0.f), fmaxf(r.z,0.f), fmaxf(r.w,0.f));
    }
    #pragma unroll
    for (int o = 16; o; o >>= 1) dot += __shfl_xor_sync(0xffffffffu, dot, o);
    if (!lane) {
        float cf = dot + cbv[0];
        out_conf[row] = cf;
        g_wexp[row]   = expf(cf);
    }
}

__global__ void k_cluster(const float* __restrict__ loc, const int* __restrict__ idx_agg,
                          float* __restrict__ out_idx) {
    int p    = blockIdx.x*8 + (threadIdx.x>>5);
    int lane = threadIdx.x & 31;
    int b    = p >> 16;
    int cell = grid_cell(loc[2*p], loc[2*p+1], HC, WC);
    int i    = idx_agg[p];
    float w  = g_wexp[(size_t)b*NN + i];
    const float4* src = (const float4*)(g_tokn + ((size_t)b*NN + i)*COUT);
    float* dst = g_cnum + ((size_t)b*NS + cell)*COUT;
    #pragma unroll
    for (int q = 0; q < 2; q++) {
        int c4 = q*32 + lane;
        float4 v = src[c4];
        red_add4(dst + c4*4, make_float4(v.x*w, v.y*w, v.z*w, v.w*w));
    }
    if (!lane) {
        atomicAdd(&g_cden[(size_t)b*NS + cell], w);
        g_wpt[p]   = w;
        out_idx[p] = (float)cell;
    }
}

__global__ void k_xdown(float* __restrict__ out_xd) {
    int row  = blockIdx.x*8 + (threadIdx.x>>5);
    int lane = threadIdx.x & 31;
    float rcp = 1.f/(g_cden[row] + EPSV);
    const float4* src = (const float4*)(g_cnum + (size_t)row*COUT);
    float4* dst = (float4*)(out_xd + (size_t)row*COUT);
    #pragma unroll
    for (int q = 0; q < 2; q++) {
        int c4 = q*32 + lane;
        float4 v = src[c4];
        dst[c4] = make_float4(fmaxf(v.x*rcp,0.f), fmaxf(v.y*rcp,0.f),
                              fmaxf(v.z*rcp,0.f), fmaxf(v.w*rcp,0.f));
    }
}

__global__ void k_aggmax(const float* __restrict__ loc, const float* __restrict__ aggw) {
    __shared__ float sm[256];
    int p = blockIdx.x*256 + threadIdx.x;
    int b = p >> 16;
    int cell = grid_cell(loc[2*p], loc[2*p+1], HC, WC);
    float aw = aggw[p] * g_wpt[p] / (g_cden[(size_t)b*NS + cell] + EPSV);
    g_wpt[p] = aw;
    sm[threadIdx.x] = aw;
    __syncthreads();
    for (int s = 128; s; s >>= 1) {
        if (threadIdx.x < s) sm[threadIdx.x] = fmaxf(sm[threadIdx.x], sm[threadIdx.x+s]);
        __syncthreads();
    }
    if (!threadIdx.x) atomicMax(&g_maxw[b], __float_as_uint(sm[0]));
}

__global__ void k_aggnorm(float* __restrict__ out_aw) {
    int p = blockIdx.x*256 + threadIdx.x;
    int b = p >> 16;
    out_aw[p] = g_wpt[p] / __uint_as_float(g_maxw[b]);
}

// ---------------- launch ----------------
extern "C" void kernel_launch(void* const* d_in, const int* in_sizes, int n_in,
                              void* d_out, int out_size) {
    const float* x      = (const float*)d_in[0];
    const float* loc    = (const float*)d_in[1];
    const int*   idxa   = (const int*)  d_in[2];
    const float* aggw   = (const float*)d_in[3];
    const float* conv_w = (const float*)d_in[4];
    const float* conv_b = (const float*)d_in[5];
    const float* skip_w = (const float*)d_in[6];
    const float* gamma  = (const float*)d_in[7];
    const float* beta   = (const float*)d_in[8];
    const float* conf_w = (const float*)d_in[9];
    const float* conf_b = (const float*)d_in[10];

    float* out      = (float*)d_out;
    float* out_xd   = out;                                    // [4,4096,256]
    float* out_xout = out + (size_t)BB*NS*COUT;               // [4,16384,256]
    float* out_conf = out_xout + (size_t)BB*NN*COUT;          // [4,16384,1]
    float* out_aw   = out_conf + (size_t)BB*NN;               // [4,65536,1]
    float* out_idx  = out_aw   + (size_t)BB*NP;               // [4,65536]

    k_zero<<<2048, 256>>>();
    k_token2map<<<BB*NP/8, 256>>>(x, loc, idxa);
    k_norm<<<(BB*HH*WW*CIN/4)/256, 256>>>();
    k_transpose<<<CIN*COUT/256, 256>>>(skip_w);
    k_conv<<<dim3(HD, 2, BB), 256>>>(conv_w, conv_b);
    k_map2token<<<BB*NP/8, 256>>>(loc, idxa, aggw);
    k_skip<<<dim3(BB*NN/64, COUT/64), 256>>>(x);
    k_bnstats<<<BB*NN/256, 256>>>();
    k_bnfinal<<<1, 256>>>(gamma, beta);
    k_bnconf<<<BB*NN/8, 256>>>(conf_w, conf_b, out_xout, out_conf);
    k_cluster<<<BB*NP/8, 256>>>(loc, idxa, out_idx);
    k_xdown<<<BB*NS/8, 256>>>(out_xd);
    k_aggmax<<<BB*NP/256, 256>>>(loc, aggw);
    k_aggnorm<<<BB*NP/256, 256>>>(out_aw);
}

// round 5
// speedup vs baseline: 1.6277x; 1.6277x over previous
#include <cuda_runtime.h>
#include <math.h>
#include <stdint.h>

#define BB   4
#define NN   16384
#define CIN  128
#define COUT 256
#define HH   256
#define WW   256
#define NP   65536      // N0 = H*W points
#define HD   128
#define WD   128
#define HC   64
#define WC   64
#define NS   4096       // HC*WC
#define EPSV 1e-6f
#define KTOT 1152       // 9*CIN
#define SLABS 36        // KTOT/32

// ---------------- scratch (device globals: no allocation allowed) ----------------
__device__ float  g_ssum[(size_t)BB*HH*WW*CIN];   // token2map sum -> normalized tf32 map (128MB)
__device__ float  g_cnt [(size_t)BB*HH*WW];       // token2map count
__device__ float  g_y   [(size_t)BB*HD*WD*COUT];  // conv output        (64MB)
__device__ float  g_num [(size_t)BB*NN*COUT];     // map2token num -> tok (64MB)
__device__ float  g_den [(size_t)BB*NN];
__device__ float  g_tokn[(size_t)BB*NN*COUT];     // BN-normalized tokens (64MB)
__device__ float  g_wexp[(size_t)BB*NN];          // exp(conf)
__device__ double g_bnsum[COUT];
__device__ double g_bnsq [COUT];
__device__ float  g_scale[COUT];
__device__ float  g_shift[COUT];
__device__ float  g_cnum[(size_t)BB*NS*COUT];     // cluster num (16MB)
__device__ float  g_cden[(size_t)BB*NS];
__device__ float  g_wpt [(size_t)BB*NP];          // per-point weight, reused
__device__ unsigned g_maxw[BB];
__device__ float  g_wT  [CIN*COUT];               // skip_w transposed [k][n]
__device__ float4 g_wBp [(size_t)SLABS*2048];     // conv weights, pre-swizzled smem image per slab

// ---------------- helpers ----------------
__device__ __forceinline__ void red_add4(float* p, float4 v) {
    asm volatile("red.global.add.v4.f32 [%0], {%1,%2,%3,%4};"
                 :: "l"(__cvta_generic_to_global(p)),
                    "f"(v.x), "f"(v.y), "f"(v.z), "f"(v.w) : "memory");
}

__device__ __forceinline__ int grid_cell(float lx, float ly, int Hg, int Wg) {
    lx = fminf(fmaxf(lx, -1.f), 1.f);
    ly = fminf(fmaxf(ly, -1.f), 1.f);
    int px = min(max(__float2int_rn(0.5f*(lx+1.f)*(float)Wg - 0.5f), 0), Wg-1);
    int py = min(max(__float2int_rn(0.5f*(ly+1.f)*(float)Hg - 0.5f), 0), Hg-1);
    return py*Wg + px;
}

__device__ __forceinline__ float to_tf32(float x) {
    uint32_t u; asm("cvt.rna.tf32.f32 %0, %1;" : "=r"(u) : "f"(x));
    return __uint_as_float(u);
}
__device__ __forceinline__ float4 tf4(float4 v) {
    return make_float4(to_tf32(v.x), to_tf32(v.y), to_tf32(v.z), to_tf32(v.w));
}

__device__ __forceinline__ uint32_t smem_u32(const void* p) {
    uint32_t a;
    asm("{ .reg .u64 t; cvta.to.shared.u64 t, %1; cvt.u32.u64 %0, t; }" : "=r"(a) : "l"(p));
    return a;
}

__device__ __forceinline__ void cpa16(uint32_t dst, const float* src, int srcsz) {
    asm volatile("cp.async.cg.shared.global [%0], [%1], 16, %2;"
                 :: "r"(dst), "l"(__cvta_generic_to_global(src)), "r"(srcsz) : "memory");
}

__device__ __forceinline__ void mma8(float& d0, float& d1, float& d2, float& d3,
                                     float a0, float a1, float a2, float a3,
                                     float b0, float b1) {
    asm volatile("mma.sync.aligned.m16n8k8.row.col.f32.tf32.tf32.f32 "
                 "{%0,%1,%2,%3},{%4,%5,%6,%7},{%8,%9},{%0,%1,%2,%3};"
                 : "+f"(d0), "+f"(d1), "+f"(d2), "+f"(d3)
                 : "r"(__float_as_uint(a0)), "r"(__float_as_uint(a1)),
                   "r"(__float_as_uint(a2)), "r"(__float_as_uint(a3)),
                   "r"(__float_as_uint(b0)), "r"(__float_as_uint(b1)));
}

// ---------------- kernels ----------------
__global__ void k_zero() {
    size_t t = (size_t)blockIdx.x*blockDim.x + threadIdx.x;
    size_t stride = (size_t)gridDim.x*blockDim.x;
    float4 z = make_float4(0.f,0.f,0.f,0.f);
    for (size_t i=t; i < (size_t)BB*HH*WW*CIN/4; i+=stride) ((float4*)g_ssum)[i]=z;
    for (size_t i=t; i < (size_t)BB*HH*WW/4;     i+=stride) ((float4*)g_cnt )[i]=z;
    for (size_t i=t; i < (size_t)BB*NN*COUT/4;   i+=stride) ((float4*)g_num )[i]=z;
    for (size_t i=t; i < (size_t)BB*NN/4;        i+=stride) ((float4*)g_den )[i]=z;
    for (size_t i=t; i < (size_t)BB*NS*COUT/4;   i+=stride) ((float4*)g_cnum)[i]=z;
    for (size_t i=t; i < (size_t)BB*NS/4;        i+=stride) ((float4*)g_cden)[i]=z;
    if (t < COUT) { g_bnsum[t]=0.0; g_bnsq[t]=0.0; }
    if (t < BB)   g_maxw[t]=0u;
}

// scatter token features to H x W map (sum + count)
__global__ void k_token2map(const float* __restrict__ x, const float* __restrict__ loc,
                            const int* __restrict__ idx_agg) {
    int p    = blockIdx.x*8 + (threadIdx.x>>5);
    int lane = threadIdx.x & 31;
    int b    = p >> 16;
    float lx = loc[2*p], ly = loc[2*p+1];
    int cell = grid_cell(lx, ly, HH, WW);
    int i    = idx_agg[p];
    const float4* src = (const float4*)(x + ((size_t)b*NN + i)*CIN);
    float* dst = g_ssum + ((size_t)b*HH*WW + cell)*CIN;
    float4 v = src[lane];
    red_add4(dst + lane*4, v);
    if (!lane) atomicAdd(&g_cnt[(size_t)b*HH*WW + cell], 1.0f);
}

// normalize map in place AND round to tf32: ssum = tf32(ssum / (cnt + eps))
__global__ void k_norm() {
    size_t i = (size_t)blockIdx.x*256 + threadIdx.x;
    float rcp = 1.f/(g_cnt[i >> 5] + EPSV);
    float4 v = ((float4*)g_ssum)[i];
    v.x*=rcp; v.y*=rcp; v.z*=rcp; v.w*=rcp;
    ((float4*)g_ssum)[i] = tf4(v);
}

__global__ void k_transpose(const float* __restrict__ w) { // skip_w[COUT][CIN] -> g_wT[CIN][COUT]
    int t = blockIdx.x*blockDim.x + threadIdx.x;
    g_wT[t] = w[(t % COUT)*CIN + (t / COUT)];
}

// conv_w [k=tap*CIN+cin][COUT] -> per-slab smem fragment image, tf32-rounded.
// image float4 index within slab: fi = nt*64 + h2*32 + g*4 + c
// value = { W[k0][n], W[k0+4][n], W[k0+8][n], W[k0+12][n] }, n=nt*8+g, k0=s*32+h2*16+c
__global__ void k_prepB(const float* __restrict__ cw) {
    int fi = blockIdx.x*256 + threadIdx.x;            // SLABS*2048 total
    int s  = fi >> 11, r = fi & 2047;
    int nt = r >> 6, h2 = (r >> 5) & 1, g = (r >> 2) & 7, c = r & 3;
    int n  = nt*8 + g;
    int k0 = s*32 + h2*16 + c;
    float4 v = make_float4(cw[(size_t)k0*COUT + n],      cw[(size_t)(k0+4)*COUT + n],
                           cw[(size_t)(k0+8)*COUT + n],  cw[(size_t)(k0+12)*COUT + n]);
    g_wBp[fi] = tf4(v);
}

// ---- 3x3 stride-2 conv as implicit GEMM on mma.sync TF32, cp.async pipeline ----
// CTA: oy=blockIdx.x, b=blockIdx.y. M=128 pixels (ox), N=256 couts, K=1152 = 36 x K32.
// smem: A[2][128][32]f (swizzled 16B chunks), B[2][2048]float4, bias[256]f
#define CV_A(buf)  ((buf)*16384)
#define CV_B(buf)  (32768 + (buf)*32768)
#define CV_BIAS    98304
#define CV_SMEM    (98304 + 1024)

__device__ __forceinline__ void cv_stage(char* smem, uint32_t sb, int s, int buf,
                                         int oy, const float* __restrict__ xin, int tid) {
    int tap = s >> 2, cinb = (s & 3) * 32;
    int ky = tap / 3, kx = tap - 3*ky;
    int iy = 2*oy - 1 + ky;
    bool iyok = (unsigned)iy < HH;
    int r = tid >> 1, q0 = (tid & 1) * 4;
    int ix = 2*r - 1 + kx;
    bool ok = iyok && ((unsigned)ix < WW);
    const float* src = xin + ((size_t)(iyok ? iy : 0)*WW + (ok ? ix : 0))*CIN + cinb;
    uint32_t dstA = sb + CV_A(buf) + r*128;
    int sz = ok ? 16 : 0;
    int sw = r & 7;
    #pragma unroll
    for (int j = 0; j < 4; j++) {
        int q = q0 + j;
        cpa16(dstA + ((q ^ sw) * 16), src + q*4, sz);
    }
    const float4* bsrc = g_wBp + (size_t)s*2048 + tid*8;
    uint32_t dstB = sb + CV_B(buf) + tid*128;
    #pragma unroll
    for (int j = 0; j < 8; j++)
        cpa16(dstB + j*16, (const float*)(bsrc + j), 16);
    asm volatile("cp.async.commit_group;" ::: "memory");
}

__device__ __forceinline__ float ldsA(const float* sA, int r, int k) {
    int kk = ((((k >> 2) ^ (r & 7)) << 2) | (k & 3));
    return sA[r*32 + kk];
}

__global__ void __launch_bounds__(256, 1) k_conv(const float* __restrict__ cb) {
    extern __shared__ char smem[];
    uint32_t sb = smem_u32(smem);
    int tid = threadIdx.x, w = tid >> 5, lane = tid & 31;
    int g = lane >> 2, cl = lane & 3;
    int wm = w & 1, wn = w >> 1;                 // warp tile 64m x 64n
    int oy = blockIdx.x, b = blockIdx.y;
    const float* xin = g_ssum + (size_t)b*HH*WW*CIN;

    *(float*)(smem + CV_BIAS + tid*4) = cb[tid];

    float acc[4][8][4];
    #pragma unroll
    for (int mt=0;mt<4;mt++) for (int nt=0;nt<8;nt++) for (int r2=0;r2<4;r2++) acc[mt][nt][r2]=0.f;

    cv_stage(smem, sb, 0, 0, oy, xin, tid);
    cv_stage(smem, sb, 1, 1, oy, xin, tid);

    for (int s = 0; s < SLABS; s++) {
        if (s < SLABS-2) asm volatile("cp.async.wait_group 1;" ::: "memory");
        else             asm volatile("cp.async.wait_group 0;" ::: "memory");
        __syncthreads();
        int buf = s & 1;
        const float*  sA = (const float*) (smem + CV_A(buf));
        const float4* sB = (const float4*)(smem + CV_B(buf));
        #pragma unroll
        for (int h2 = 0; h2 < 2; h2++) {
            float4 bv[8];
            #pragma unroll
            for (int nt = 0; nt < 8; nt++)
                bv[nt] = sB[(wn*8 + nt)*64 + h2*32 + g*4 + cl];
            #pragma unroll
            for (int hh = 0; hh < 2; hh++) {
                int kc = (h2*2 + hh)*8 + cl;
                float a[4][4];
                #pragma unroll
                for (int mt = 0; mt < 4; mt++) {
                    int r0 = wm*64 + mt*16 + g;
                    a[mt][0] = ldsA(sA, r0,     kc);
                    a[mt][1] = ldsA(sA, r0 + 8, kc);
                    a[mt][2] = ldsA(sA, r0,     kc + 4);
                    a[mt][3] = ldsA(sA, r0 + 8, kc + 4);
                }
                #pragma unroll
                for (int mt = 0; mt < 4; mt++)
                    #pragma unroll
                    for (int nt = 0; nt < 8; nt++) {
                        float b0 = hh ? bv[nt].z : bv[nt].x;
                        float b1 = hh ? bv[nt].w : bv[nt].y;
                        mma8(acc[mt][nt][0], acc[mt][nt][1], acc[mt][nt][2], acc[mt][nt][3],
                             a[mt][0], a[mt][1], a[mt][2], a[mt][3], b0, b1);
                    }
            }
        }
        __syncthreads();
        if (s + 2 < SLABS) cv_stage(smem, sb, s + 2, buf, oy, xin, tid);
    }

    // epilogue: D frag (m16n8): d0,d1 @ (g, 2c+{0,1}); d2,d3 @ (g+8, 2c+{0,1})
    const float* bias = (const float*)(smem + CV_BIAS);
    float* ybase = g_y + (((size_t)b*HD + oy)*WD)*COUT;
    #pragma unroll
    for (int mt = 0; mt < 4; mt++) {
        int ox0 = wm*64 + mt*16 + g;
        #pragma unroll
        for (int nt = 0; nt < 8; nt++) {
            int n = wn*64 + nt*8 + cl*2;
            float b0 = bias[n], b1 = bias[n+1];
            *(float2*)(ybase + (size_t)ox0*COUT + n)     = make_float2(acc[mt][nt][0]+b0, acc[mt][nt][1]+b1);
            *(float2*)(ybase + (size_t)(ox0+8)*COUT + n) = make_float2(acc[mt][nt][2]+b0, acc[mt][nt][3]+b1);
        }
    }
}

// bilinear gather from conv map at orig points, weighted scatter to tokens
__global__ void k_map2token(const float* __restrict__ loc, const int* __restrict__ idx_agg,
                            const float* __restrict__ aggw) {
    int p    = blockIdx.x*8 + (threadIdx.x>>5);
    int lane = threadIdx.x & 31;
    int b    = p >> 16;
    float lx = fminf(fmaxf(loc[2*p],   -1.f), 1.f);
    float ly = fminf(fmaxf(loc[2*p+1], -1.f), 1.f);
    float fx = fminf(fmaxf(0.5f*(lx+1.f)*(float)WD - 0.5f, 0.f), (float)(WD-1));
    float fy = fminf(fmaxf(0.5f*(ly+1.f)*(float)HD - 0.5f, 0.f), (float)(HD-1));
    float x0f = floorf(fx), y0f = floorf(fy);
    float wx = fx - x0f, wy = fy - y0f;
    int x0 = (int)x0f, y0 = (int)y0f;
    int x1 = min(x0+1, WD-1), y1 = min(y0+1, HD-1);
    const float* base = g_y + (size_t)b*HD*WD*COUT;
    const float4* r00 = (const float4*)(base + (size_t)(y0*WD+x0)*COUT);
    const float4* r01 = (const float4*)(base + (size_t)(y0*WD+x1)*COUT);
    const float4* r10 = (const float4*)(base + (size_t)(y1*WD+x0)*COUT);
    const float4* r11 = (const float4*)(base + (size_t)(y1*WD+x1)*COUT);
    float w00=(1.f-wx)*(1.f-wy), w01=wx*(1.f-wy), w10=(1.f-wx)*wy, w11=wx*wy;
    float wpt = aggw[p];
    int i = idx_agg[p];
    float* dst = g_num + ((size_t)b*NN + i)*COUT;
    #pragma unroll
    for (int q = 0; q < 2; q++) {
        int c4 = q*32 + lane;
        float4 a = r00[c4], bq = r01[c4], cc = r10[c4], d = r11[c4];
        float4 f;
        f.x = (w00*a.x + w01*bq.x + w10*cc.x + w11*d.x)*wpt;
        f.y = (w00*a.y + w01*bq.y + w10*cc.y + w11*d.y)*wpt;
        f.z = (w00*a.z + w01*bq.z + w10*cc.z + w11*d.z)*wpt;
        f.w = (w00*a.w + w01*bq.w + w10*cc.w + w11*d.w)*wpt;
        red_add4(dst + c4*4, f);
    }
    if (!lane) atomicAdd(&g_den[(size_t)b*NN + i], wpt);
}

// skip GEMM (x @ skip_w^T) fused with tok = num/(den+eps) + skip -> overwrite g_num
__global__ void __launch_bounds__(256) k_skip(const float* __restrict__ x) {
    __shared__ __align__(16) float As2[16][68];
    __shared__ __align__(16) float Bs2[16][64];
    int m0 = blockIdx.x*64, n0 = blockIdx.y*64;
    int tid = threadIdx.x;
    int tx = tid & 15, ty = tid >> 4;
    int m_l = tid >> 2, kq = (tid & 3)*4;
    int kb  = tid >> 4, nb = (tid & 15)*4;
    float acc[4][4] = {};
    const float* arow = x + (size_t)(m0 + m_l)*CIN;
    for (int cc = 0; cc < 8; cc++) {
        float4 va = *(const float4*)(arow + cc*16 + kq);
        __syncthreads();
        As2[kq+0][m_l]=va.x; As2[kq+1][m_l]=va.y; As2[kq+2][m_l]=va.z; As2[kq+3][m_l]=va.w;
        *(float4*)&Bs2[kb][nb] = *(const float4*)(g_wT + (size_t)(cc*16+kb)*COUT + n0 + nb);
        __syncthreads();
        #pragma unroll
        for (int k = 0; k < 16; k++) {
            float4 a  = *(float4*)&As2[k][ty*4];
            float4 bv = *(float4*)&Bs2[k][tx*4];
            acc[0][0]+=a.x*bv.x; acc[0][1]+=a.x*bv.y; acc[0][2]+=a.x*bv.z; acc[0][3]+=a.x*bv.w;
            acc[1][0]+=a.y*bv.x; acc[1][1]+=a.y*bv.y; acc[1][2]+=a.y*bv.z; acc[1][3]+=a.y*bv.w;
            acc[2][0]+=a.z*bv.x; acc[2][1]+=a.z*bv.y; acc[2][2]+=a.z*bv.z; acc[2][3]+=a.z*bv.w;
            acc[3][0]+=a.w*bv.x; acc[3][1]+=a.w*bv.y; acc[3][2]+=a.w*bv.z; acc[3][3]+=a.w*bv.w;
        }
    }
    #pragma unroll
    for (int i2 = 0; i2 < 4; i2++) {
        int row = m0 + ty*4 + i2;
        float rcp = 1.f/(g_den[row] + EPSV);
        float* orow = g_num + (size_t)row*COUT + n0 + tx*4;
        float4 nv = *(float4*)orow;
        float4 o = make_float4(acc[i2][0] + nv.x*rcp, acc[i2][1] + nv.y*rcp,
                               acc[i2][2] + nv.z*rcp, acc[i2][3] + nv.w*rcp);
        *(float4*)orow = o;
    }
}

__global__ void k_bnstats() {
    int c  = threadIdx.x;
    int r0 = blockIdx.x*256;
    double s = 0.0, s2 = 0.0;
    for (int r = 0; r < 256; r++) {
        float v = g_num[(size_t)(r0 + r)*COUT + c];
        s += v; s2 += (double)v*v;
    }
    atomicAdd(&g_bnsum[c], s);
    atomicAdd(&g_bnsq[c],  s2);
}

__global__ void k_bnfinal(const float* __restrict__ gam, const float* __restrict__ bet) {
    int c = threadIdx.x;
    double m  = (double)BB*NN;
    double mu = g_bnsum[c]/m;
    double var = g_bnsq[c]/m - mu*mu;
    float sc = gam[c] * (float)(1.0/sqrt(var + 1e-5));
    g_scale[c] = sc;
    g_shift[c] = bet[c] - (float)mu*sc;
}

__global__ void k_bnconf(const float* __restrict__ cw, const float* __restrict__ cbv,
                         float* __restrict__ out_xout, float* __restrict__ out_conf) {
    int row  = blockIdx.x*8 + (threadIdx.x>>5);
    int lane = threadIdx.x & 31;
    const float4* t  = (const float4*)(g_num  + (size_t)row*COUT);
    float4* tn       = (float4*)(g_tokn + (size_t)row*COUT);
    float4* xo       = (float4*)(out_xout + (size_t)row*COUT);
    float dot = 0.f;
    #pragma unroll
    for (int q = 0; q < 2; q++) {
        int c4 = q*32 + lane;
        float4 v  = t[c4];
        float4 sc = ((const float4*)g_scale)[c4];
        float4 sh = ((const float4*)g_shift)[c4];
        float4 w  = ((const float4*)cw)[c4];
        float4 r = make_float4(v.x*sc.x+sh.x, v.y*sc.y+sh.y, v.z*sc.z+sh.z, v.w*sc.w+sh.w);
        dot += r.x*w.x + r.y*w.y + r.z*w.z + r.w*w.w;
        tn[c4] = r;
        xo[c4] = make_float4(fmaxf(r.x,0.f), fmaxf(r.y,0.f), fmaxf(r.z,0.f), fmaxf(r.w,0.f));
    }
    #pragma unroll
    for (int o = 16; o; o >>= 1) dot += __shfl_xor_sync(0xffffffffu, dot, o);
    if (!lane) {
        float cf = dot + cbv[0];
        out_conf[row] = cf;
        g_wexp[row]   = expf(cf);
    }
}

__global__ void k_cluster(const float* __restrict__ loc, const int* __restrict__ idx_agg,
                          float* __restrict__ out_idx) {
    int p    = blockIdx.x*8 + (threadIdx.x>>5);
    int lane = threadIdx.x & 31;
    int b    = p >> 16;
    int cell = grid_cell(loc[2*p], loc[2*p+1], HC, WC);
    int i    = idx_agg[p];
    float w  = g_wexp[(size_t)b*NN + i];
    const float4* src = (const float4*)(g_tokn + ((size_t)b*NN + i)*COUT);
    float* dst = g_cnum + ((size_t)b*NS + cell)*COUT;
    #pragma unroll
    for (int q = 0; q < 2; q++) {
        int c4 = q*32 + lane;
        float4 v = src[c4];
        red_add4(dst + c4*4, make_float4(v.x*w, v.y*w, v.z*w, v.w*w));
    }
    if (!lane) {
        atomicAdd(&g_cden[(size_t)b*NS + cell], w);
        g_wpt[p]   = w;
        out_idx[p] = (float)cell;
    }
}

__global__ void k_xdown(float* __restrict__ out_xd) {
    int row  = blockIdx.x*8 + (threadIdx.x>>5);
    int lane = threadIdx.x & 31;
    float rcp = 1.f/(g_cden[row] + EPSV);
    const float4* src = (const float4*)(g_cnum + (size_t)row*COUT);
    float4* dst = (float4*)(out_xd + (size_t)row*COUT);
    #pragma unroll
    for (int q = 0; q < 2; q++) {
        int c4 = q*32 + lane;
        float4 v = src[c4];
        dst[c4] = make_float4(fmaxf(v.x*rcp,0.f), fmaxf(v.y*rcp,0.f),
                              fmaxf(v.z*rcp,0.f), fmaxf(v.w*rcp,0.f));
    }
}

__global__ void k_aggmax(const float* __restrict__ loc, const float* __restrict__ aggw) {
    __shared__ float sm[256];
    int p = blockIdx.x*256 + threadIdx.x;
    int b = p >> 16;
    int cell = grid_cell(loc[2*p], loc[2*p+1], HC, WC);
    float aw = aggw[p] * g_wpt[p] / (g_cden[(size_t)b*NS + cell] + EPSV);
    g_wpt[p] = aw;
    sm[threadIdx.x] = aw;
    __syncthreads();
    for (int s = 128; s; s >>= 1) {
        if (threadIdx.x < s) sm[threadIdx.x] = fmaxf(sm[threadIdx.x], sm[threadIdx.x+s]);
        __syncthreads();
    }
    if (!threadIdx.x) atomicMax(&g_maxw[b], __float_as_uint(sm[0]));
}

__global__ void k_aggnorm(float* __restrict__ out_aw) {
    int p = blockIdx.x*256 + threadIdx.x;
    int b = p >> 16;
    out_aw[p] = g_wpt[p] / __uint_as_float(g_maxw[b]);
}

// ---------------- launch ----------------
extern "C" void kernel_launch(void* const* d_in, const int* in_sizes, int n_in,
                              void* d_out, int out_size) {
    const float* x      = (const float*)d_in[0];
    const float* loc    = (const float*)d_in[1];
    const int*   idxa   = (const int*)  d_in[2];
    const float* aggw   = (const float*)d_in[3];
    const float* conv_w = (const float*)d_in[4];
    const float* conv_b = (const float*)d_in[5];
    const float* skip_w = (const float*)d_in[6];
    const float* gamma  = (const float*)d_in[7];
    const float* beta   = (const float*)d_in[8];
    const float* conf_w = (const float*)d_in[9];
    const float* conf_b = (const float*)d_in[10];

    float* out      = (float*)d_out;
    float* out_xd   = out;                                    // [4,4096,256]
    float* out_xout = out + (size_t)BB*NS*COUT;               // [4,16384,256]
    float* out_conf = out_xout + (size_t)BB*NN*COUT;          // [4,16384,1]
    float* out_aw   = out_conf + (size_t)BB*NN;               // [4,65536,1]
    float* out_idx  = out_aw   + (size_t)BB*NP;               // [4,65536]

    cudaFuncSetAttribute(k_conv, cudaFuncAttributeMaxDynamicSharedMemorySize, CV_SMEM);

    k_zero<<<2048, 256>>>();
    k_token2map<<<BB*NP/8, 256>>>(x, loc, idxa);
    k_norm<<<(BB*HH*WW*CIN/4)/256, 256>>>();
    k_transpose<<<CIN*COUT/256, 256>>>(skip_w);
    k_prepB<<<SLABS*2048/256, 256>>>(conv_w);
    k_conv<<<dim3(HD, BB), 256, CV_SMEM>>>(conv_b);
    k_map2token<<<BB*NP/8, 256>>>(loc, idxa, aggw);
    k_skip<<<dim3(BB*NN/64, COUT/64), 256>>>(x);
    k_bnstats<<<BB*NN/256, 256>>>();
    k_bnfinal<<<1, 256>>>(gamma, beta);
    k_bnconf<<<BB*NN/8, 256>>>(conf_w, conf_b, out_xout, out_conf);
    k_cluster<<<BB*NP/8, 256>>>(loc, idxa, out_idx);
    k_xdown<<<BB*NS/8, 256>>>(out_xd);
    k_aggmax<<<BB*NP/256, 256>>>(loc, aggw);
    k_aggnorm<<<BB*NP/256, 256>>>(out_aw);
}

// round 6
// speedup vs baseline: 1.6409x; 1.0081x over previous
#include <cuda_runtime.h>
#include <math.h>
#include <stdint.h>

#define BB   4
#define NN   16384
#define CIN  128
#define COUT 256
#define HH   256
#define WW   256
#define NP   65536      // N0 = H*W points
#define HD   128
#define WD   128
#define HC   64
#define WC   64
#define NS   4096       // HC*WC
#define EPSV 1e-6f
#define KTOT 1152       // 9*CIN
#define SLABS 36        // KTOT/32

// ---------------- scratch (device globals: no allocation allowed) ----------------
__device__ float  g_ssum[(size_t)BB*HH*WW*CIN];   // token2map sum -> normalized tf32 map (128MB)
__device__ float  g_cnt [(size_t)BB*HH*WW];       // token2map count
__device__ float  g_y   [(size_t)BB*HD*WD*COUT];  // conv output        (64MB)
__device__ float  g_num [(size_t)BB*NN*COUT];     // map2token num -> tok (64MB)
__device__ float  g_den [(size_t)BB*NN];
__device__ float  g_tokn[(size_t)BB*NN*COUT];     // BN-normalized tokens (64MB)
__device__ float  g_wexp[(size_t)BB*NN];          // exp(conf)
__device__ double g_bnsum[COUT];
__device__ double g_bnsq [COUT];
__device__ float  g_scale[COUT];
__device__ float  g_shift[COUT];
__device__ float  g_cnum[(size_t)BB*NS*COUT];     // cluster num (16MB)
__device__ float  g_cden[(size_t)BB*NS];
__device__ float  g_wpt [(size_t)BB*NP];          // per-point weight, reused
__device__ unsigned g_maxw[BB];
__device__ float  g_wT  [CIN*COUT];               // skip_w transposed [k][n]
__device__ float4 g_wBp [(size_t)SLABS*2048];     // conv weights, pre-swizzled smem image per slab

// ---------------- helpers ----------------
__device__ __forceinline__ void red_add4(float* p, float4 v) {
    asm volatile("red.global.add.v4.f32 [%0], {%1,%2,%3,%4};"
                 :: "l"(__cvta_generic_to_global(p)),
                    "f"(v.x), "f"(v.y), "f"(v.z), "f"(v.w) : "memory");
}

__device__ __forceinline__ int grid_cell(float lx, float ly, int Hg, int Wg) {
    lx = fminf(fmaxf(lx, -1.f), 1.f);
    ly = fminf(fmaxf(ly, -1.f), 1.f);
    int px = min(max(__float2int_rn(0.5f*(lx+1.f)*(float)Wg - 0.5f), 0), Wg-1);
    int py = min(max(__float2int_rn(0.5f*(ly+1.f)*(float)Hg - 0.5f), 0), Hg-1);
    return py*Wg + px;
}

__device__ __forceinline__ float to_tf32(float x) {
    uint32_t u; asm("cvt.rna.tf32.f32 %0, %1;" : "=r"(u) : "f"(x));
    return __uint_as_float(u);
}
__device__ __forceinline__ float4 tf4(float4 v) {
    return make_float4(to_tf32(v.x), to_tf32(v.y), to_tf32(v.z), to_tf32(v.w));
}

__device__ __forceinline__ uint32_t smem_u32(const void* p) {
    uint32_t a;
    asm("{ .reg .u64 t; cvta.to.shared.u64 t, %1; cvt.u32.u64 %0, t; }" : "=r"(a) : "l"(p));
    return a;
}

__device__ __forceinline__ void cpa16(uint32_t dst, const float* src, int srcsz) {
    asm volatile("cp.async.cg.shared.global [%0], [%1], 16, %2;"
                 :: "r"(dst), "l"(__cvta_generic_to_global(src)), "r"(srcsz) : "memory");
}

__device__ __forceinline__ void mma8(float& d0, float& d1, float& d2, float& d3,
                                     float a0, float a1, float a2, float a3,
                                     float b0, float b1) {
    asm volatile("mma.sync.aligned.m16n8k8.row.col.f32.tf32.tf32.f32 "
                 "{%0,%1,%2,%3},{%4,%5,%6,%7},{%8,%9},{%0,%1,%2,%3};"
                 : "+f"(d0), "+f"(d1), "+f"(d2), "+f"(d3)
                 : "r"(__float_as_uint(a0)), "r"(__float_as_uint(a1)),
                   "r"(__float_as_uint(a2)), "r"(__float_as_uint(a3)),
                   "r"(__float_as_uint(b0)), "r"(__float_as_uint(b1)));
}

// ---------------- kernels ----------------
// fused: zero all accumulators + transpose skip_w + build pre-swizzled conv-B image
__global__ void k_init(const float* __restrict__ skw, const float* __restrict__ cw) {
    size_t t = (size_t)blockIdx.x*blockDim.x + threadIdx.x;
    size_t stride = (size_t)gridDim.x*blockDim.x;
    float4 z = make_float4(0.f,0.f,0.f,0.f);
    for (size_t i=t; i < (size_t)BB*HH*WW*CIN/4; i+=stride) ((float4*)g_ssum)[i]=z;
    for (size_t i=t; i < (size_t)BB*HH*WW/4;     i+=stride) ((float4*)g_cnt )[i]=z;
    for (size_t i=t; i < (size_t)BB*NN*COUT/4;   i+=stride) ((float4*)g_num )[i]=z;
    for (size_t i=t; i < (size_t)BB*NN/4;        i+=stride) ((float4*)g_den )[i]=z;
    for (size_t i=t; i < (size_t)BB*NS*COUT/4;   i+=stride) ((float4*)g_cnum)[i]=z;
    for (size_t i=t; i < (size_t)BB*NS/4;        i+=stride) ((float4*)g_cden)[i]=z;
    if (t < COUT) { g_bnsum[t]=0.0; g_bnsq[t]=0.0; }
    if (t < BB)   g_maxw[t]=0u;
    if (t < CIN*COUT)
        g_wT[t] = skw[((int)t % COUT)*CIN + ((int)t / COUT)];
    if (t < (size_t)SLABS*2048) {
        int fi = (int)t;
        int s  = fi >> 11, r = fi & 2047;
        int nt = r >> 6, h2 = (r >> 5) & 1, g = (r >> 2) & 7, c = r & 3;
        int n  = nt*8 + g;
        int k0 = s*32 + h2*16 + c;
        float4 v = make_float4(cw[(size_t)k0*COUT + n],      cw[(size_t)(k0+4)*COUT + n],
                               cw[(size_t)(k0+8)*COUT + n],  cw[(size_t)(k0+12)*COUT + n]);
        g_wBp[fi] = tf4(v);
    }
}

// scatter token features to H x W map (sum + count)
__global__ void k_token2map(const float* __restrict__ x, const float* __restrict__ loc,
                            const int* __restrict__ idx_agg) {
    int p    = blockIdx.x*8 + (threadIdx.x>>5);
    int lane = threadIdx.x & 31;
    int b    = p >> 16;
    float lx = loc[2*p], ly = loc[2*p+1];
    int cell = grid_cell(lx, ly, HH, WW);
    int i    = idx_agg[p];
    const float4* src = (const float4*)(x + ((size_t)b*NN + i)*CIN);
    float* dst = g_ssum + ((size_t)b*HH*WW + cell)*CIN;
    float4 v = src[lane];
    red_add4(dst + lane*4, v);
    if (!lane) atomicAdd(&g_cnt[(size_t)b*HH*WW + cell], 1.0f);
}

// normalize map in place AND round to tf32: ssum = tf32(ssum / (cnt + eps))
__global__ void k_norm() {
    size_t i = (size_t)blockIdx.x*256 + threadIdx.x;
    float rcp = 1.f/(g_cnt[i >> 5] + EPSV);
    float4 v = ((float4*)g_ssum)[i];
    v.x*=rcp; v.y*=rcp; v.z*=rcp; v.w*=rcp;
    ((float4*)g_ssum)[i] = tf4(v);
}

// ---- 3x3 stride-2 conv as implicit GEMM on mma.sync TF32, 3-stage cp.async pipeline ----
// CTA: oy=blockIdx.x, b=blockIdx.y. M=128 pixels (ox), N=256 couts, K=1152 = 36 x K32.
#define CV_BUF   49152
#define CV_A(i)  ((i)*CV_BUF)
#define CV_B(i)  ((i)*CV_BUF + 16384)
#define CV_BIAS  (3*CV_BUF)
#define CV_SMEM  (CV_BIAS + 1024)

__device__ __forceinline__ void cv_stage(char* smem, uint32_t sb, int s, int buf,
                                         int oy, const float* __restrict__ xin, int tid) {
    int tap = s >> 2, cinb = (s & 3) * 32;
    int ky = tap / 3, kx = tap - 3*ky;
    int iy = 2*oy - 1 + ky;
    bool iyok = (unsigned)iy < HH;
    int r = tid >> 1, q0 = (tid & 1) * 4;
    int ix = 2*r - 1 + kx;
    bool ok = iyok && ((unsigned)ix < WW);
    const float* src = xin + ((size_t)(iyok ? iy : 0)*WW + (ok ? ix : 0))*CIN + cinb;
    uint32_t dstA = sb + CV_A(buf) + r*128;
    int sz = ok ? 16 : 0;
    int sw = r & 7;
    #pragma unroll
    for (int j = 0; j < 4; j++) {
        int q = q0 + j;
        cpa16(dstA + ((q ^ sw) * 16), src + q*4, sz);
    }
    const float4* bsrc = g_wBp + (size_t)s*2048 + tid*8;
    uint32_t dstB = sb + CV_B(buf) + tid*128;
    #pragma unroll
    for (int j = 0; j < 8; j++)
        cpa16(dstB + j*16, (const float*)(bsrc + j), 16);
    asm volatile("cp.async.commit_group;" ::: "memory");
}

__device__ __forceinline__ float ldsA(const float* sA, int r, int k) {
    int kk = ((((k >> 2) ^ (r & 7)) << 2) | (k & 3));
    return sA[r*32 + kk];
}

__global__ void __launch_bounds__(256, 1) k_conv(const float* __restrict__ cb) {
    extern __shared__ char smem[];
    uint32_t sb = smem_u32(smem);
    int tid = threadIdx.x, w = tid >> 5, lane = tid & 31;
    int g = lane >> 2, cl = lane & 3;
    int wm = w & 1, wn = w >> 1;                 // warp tile 64m x 64n
    int oy = blockIdx.x, b = blockIdx.y;
    const float* xin = g_ssum + (size_t)b*HH*WW*CIN;

    *(float*)(smem + CV_BIAS + tid*4) = cb[tid];

    float acc[4][8][4];
    #pragma unroll
    for (int mt=0;mt<4;mt++) for (int nt=0;nt<8;nt++) for (int r2=0;r2<4;r2++) acc[mt][nt][r2]=0.f;

    cv_stage(smem, sb, 0, 0, oy, xin, tid);
    cv_stage(smem, sb, 1, 1, oy, xin, tid);

    int bufc = 0;                                  // buffer of slab s
    for (int s = 0; s < SLABS; s++) {
        if (s < SLABS-1) asm volatile("cp.async.wait_group 1;" ::: "memory");
        else             asm volatile("cp.async.wait_group 0;" ::: "memory");
        __syncthreads();
        int bufn = bufc + 2; if (bufn >= 3) bufn -= 3;
        if (s + 2 < SLABS) cv_stage(smem, sb, s + 2, bufn, oy, xin, tid);
        const float*  sA = (const float*) (smem + CV_A(bufc));
        const float4* sB = (const float4*)(smem + CV_B(bufc));
        #pragma unroll
        for (int h2 = 0; h2 < 2; h2++) {
            float4 bv[8];
            #pragma unroll
            for (int nt = 0; nt < 8; nt++)
                bv[nt] = sB[(wn*8 + nt)*64 + h2*32 + g*4 + cl];
            #pragma unroll
            for (int hh = 0; hh < 2; hh++) {
                int kc = (h2*2 + hh)*8 + cl;
                float a[4][4];
                #pragma unroll
                for (int mt = 0; mt < 4; mt++) {
                    int r0 = wm*64 + mt*16 + g;
                    a[mt][0] = ldsA(sA, r0,     kc);
                    a[mt][1] = ldsA(sA, r0 + 8, kc);
                    a[mt][2] = ldsA(sA, r0,     kc + 4);
                    a[mt][3] = ldsA(sA, r0 + 8, kc + 4);
                }
                #pragma unroll
                for (int mt = 0; mt < 4; mt++)
                    #pragma unroll
                    for (int nt = 0; nt < 8; nt++) {
                        float b0 = hh ? bv[nt].z : bv[nt].x;
                        float b1 = hh ? bv[nt].w : bv[nt].y;
                        mma8(acc[mt][nt][0], acc[mt][nt][1], acc[mt][nt][2], acc[mt][nt][3],
                             a[mt][0], a[mt][1], a[mt][2], a[mt][3], b0, b1);
                    }
            }
        }
        bufc++; if (bufc >= 3) bufc = 0;
    }

    // epilogue: D frag (m16n8): d0,d1 @ (g, 2c+{0,1}); d2,d3 @ (g+8, 2c+{0,1})
    const float* bias = (const float*)(smem + CV_BIAS);
    float* ybase = g_y + (((size_t)b*HD + oy)*WD)*COUT;
    #pragma unroll
    for (int mt = 0; mt < 4; mt++) {
        int ox0 = wm*64 + mt*16 + g;
        #pragma unroll
        for (int nt = 0; nt < 8; nt++) {
            int n = wn*64 + nt*8 + cl*2;
            float b0 = bias[n], b1 = bias[n+1];
            *(float2*)(ybase + (size_t)ox0*COUT + n)     = make_float2(acc[mt][nt][0]+b0, acc[mt][nt][1]+b1);
            *(float2*)(ybase + (size_t)(ox0+8)*COUT + n) = make_float2(acc[mt][nt][2]+b0, acc[mt][nt][3]+b1);
        }
    }
}

// bilinear gather from conv map at orig points, weighted scatter to tokens
__global__ void k_map2token(const float* __restrict__ loc, const int* __restrict__ idx_agg,
                            const float* __restrict__ aggw) {
    int p    = blockIdx.x*8 + (threadIdx.x>>5);
    int lane = threadIdx.x & 31;
    int b    = p >> 16;
    float lx = fminf(fmaxf(loc[2*p],   -1.f), 1.f);
    float ly = fminf(fmaxf(loc[2*p+1], -1.f), 1.f);
    float fx = fminf(fmaxf(0.5f*(lx+1.f)*(float)WD - 0.5f, 0.f), (float)(WD-1));
    float fy = fminf(fmaxf(0.5f*(ly+1.f)*(float)HD - 0.5f, 0.f), (float)(HD-1));
    float x0f = floorf(fx), y0f = floorf(fy);
    float wx = fx - x0f, wy = fy - y0f;
    int x0 = (int)x0f, y0 = (int)y0f;
    int x1 = min(x0+1, WD-1), y1 = min(y0+1, HD-1);
    const float* base = g_y + (size_t)b*HD*WD*COUT;
    const float4* r00 = (const float4*)(base + (size_t)(y0*WD+x0)*COUT);
    const float4* r01 = (const float4*)(base + (size_t)(y0*WD+x1)*COUT);
    const float4* r10 = (const float4*)(base + (size_t)(y1*WD+x0)*COUT);
    const float4* r11 = (const float4*)(base + (size_t)(y1*WD+x1)*COUT);
    float w00=(1.f-wx)*(1.f-wy), w01=wx*(1.f-wy), w10=(1.f-wx)*wy, w11=wx*wy;
    float wpt = aggw[p];
    int i = idx_agg[p];
    float* dst = g_num + ((size_t)b*NN + i)*COUT;
    #pragma unroll
    for (int q = 0; q < 2; q++) {
        int c4 = q*32 + lane;
        float4 a = r00[c4], bq = r01[c4], cc = r10[c4], d = r11[c4];
        float4 f;
        f.x = (w00*a.x + w01*bq.x + w10*cc.x + w11*d.x)*wpt;
        f.y = (w00*a.y + w01*bq.y + w10*cc.y + w11*d.y)*wpt;
        f.z = (w00*a.z + w01*bq.z + w10*cc.z + w11*d.z)*wpt;
        f.w = (w00*a.w + w01*bq.w + w10*cc.w + w11*d.w)*wpt;
        red_add4(dst + c4*4, f);
    }
    if (!lane) atomicAdd(&g_den[(size_t)b*NN + i], wpt);
}

// skip GEMM (x @ skip_w^T) fused with tok = num/(den+eps) + skip -> overwrite g_num
__global__ void __launch_bounds__(256) k_skip(const float* __restrict__ x) {
    __shared__ __align__(16) float As2[16][68];
    __shared__ __align__(16) float Bs2[16][64];
    int m0 = blockIdx.x*64, n0 = blockIdx.y*64;
    int tid = threadIdx.x;
    int tx = tid & 15, ty = tid >> 4;
    int m_l = tid >> 2, kq = (tid & 3)*4;
    int kb  = tid >> 4, nb = (tid & 15)*4;
    float acc[4][4] = {};
    const float* arow = x + (size_t)(m0 + m_l)*CIN;
    for (int cc = 0; cc < 8; cc++) {
        float4 va = *(const float4*)(arow + cc*16 + kq);
        __syncthreads();
        As2[kq+0][m_l]=va.x; As2[kq+1][m_l]=va.y; As2[kq+2][m_l]=va.z; As2[kq+3][m_l]=va.w;
        *(float4*)&Bs2[kb][nb] = *(const float4*)(g_wT + (size_t)(cc*16+kb)*COUT + n0 + nb);
        __syncthreads();
        #pragma unroll
        for (int k = 0; k < 16; k++) {
            float4 a  = *(float4*)&As2[k][ty*4];
            float4 bv = *(float4*)&Bs2[k][tx*4];
            acc[0][0]+=a.x*bv.x; acc[0][1]+=a.x*bv.y; acc[0][2]+=a.x*bv.z; acc[0][3]+=a.x*bv.w;
            acc[1][0]+=a.y*bv.x; acc[1][1]+=a.y*bv.y; acc[1][2]+=a.y*bv.z; acc[1][3]+=a.y*bv.w;
            acc[2][0]+=a.z*bv.x; acc[2][1]+=a.z*bv.y; acc[2][2]+=a.z*bv.z; acc[2][3]+=a.z*bv.w;
            acc[3][0]+=a.w*bv.x; acc[3][1]+=a.w*bv.y; acc[3][2]+=a.w*bv.z; acc[3][3]+=a.w*bv.w;
        }
    }
    #pragma unroll
    for (int i2 = 0; i2 < 4; i2++) {
        int row = m0 + ty*4 + i2;
        float rcp = 1.f/(g_den[row] + EPSV);
        float* orow = g_num + (size_t)row*COUT + n0 + tx*4;
        float4 nv = *(float4*)orow;
        float4 o = make_float4(acc[i2][0] + nv.x*rcp, acc[i2][1] + nv.y*rcp,
                               acc[i2][2] + nv.z*rcp, acc[i2][3] + nv.w*rcp);
        *(float4*)orow = o;
    }
}

__global__ void k_bnstats() {
    int c  = threadIdx.x;
    int r0 = blockIdx.x*256;
    double s = 0.0, s2 = 0.0;
    for (int r = 0; r < 256; r++) {
        float v = g_num[(size_t)(r0 + r)*COUT + c];
        s += v; s2 += (double)v*v;
    }
    atomicAdd(&g_bnsum[c], s);
    atomicAdd(&g_bnsq[c],  s2);
}

__global__ void k_bnfinal(const float* __restrict__ gam, const float* __restrict__ bet) {
    int c = threadIdx.x;
    double m  = (double)BB*NN;
    double mu = g_bnsum[c]/m;
    double var = g_bnsq[c]/m - mu*mu;
    float sc = gam[c] * (float)(1.0/sqrt(var + 1e-5));
    g_scale[c] = sc;
    g_shift[c] = bet[c] - (float)mu*sc;
}

__global__ void k_bnconf(const float* __restrict__ cw, const float* __restrict__ cbv,
                         float* __restrict__ out_xout, float* __restrict__ out_conf) {
    int row  = blockIdx.x*8 + (threadIdx.x>>5);
    int lane = threadIdx.x & 31;
    const float4* t  = (const float4*)(g_num  + (size_t)row*COUT);
    float4* tn       = (float4*)(g_tokn + (size_t)row*COUT);
    float4* xo       = (float4*)(out_xout + (size_t)row*COUT);
    float dot = 0.f;
    #pragma unroll
    for (int q = 0; q < 2; q++) {
        int c4 = q*32 + lane;
        float4 v  = t[c4];
        float4 sc = ((const float4*)g_scale)[c4];
        float4 sh = ((const float4*)g_shift)[c4];
        float4 w  = ((const float4*)cw)[c4];
        float4 r = make_float4(v.x*sc.x+sh.x, v.y*sc.y+sh.y, v.z*sc.z+sh.z, v.w*sc.w+sh.w);
        dot += r.x*w.x + r.y*w.y + r.z*w.z + r.w*w.w;
        tn[c4] = r;
        xo[c4] = make_float4(fmaxf(r.x,0.f), fmaxf(r.y,0.f), fmaxf(r.z,0.f), fmaxf(r.w,0.f));
    }
    #pragma unroll
    for (int o = 16; o; o >>= 1) dot += __shfl_xor_sync(0xffffffffu, dot, o);
    if (!lane) {
        float cf = dot + cbv[0];
        out_conf[row] = cf;
        g_wexp[row]   = expf(cf);
    }
}

__global__ void k_cluster(const float* __restrict__ loc, const int* __restrict__ idx_agg,
                          float* __restrict__ out_idx) {
    int p    = blockIdx.x*8 + (threadIdx.x>>5);
    int lane = threadIdx.x & 31;
    int b    = p >> 16;
    int cell = grid_cell(loc[2*p], loc[2*p+1], HC, WC);
    int i    = idx_agg[p];
    float w  = g_wexp[(size_t)b*NN + i];
    const float4* src = (const float4*)(g_tokn + ((size_t)b*NN + i)*COUT);
    float* dst = g_cnum + ((size_t)b*NS + cell)*COUT;
    #pragma unroll
    for (int q = 0; q < 2; q++) {
        int c4 = q*32 + lane;
        float4 v = src[c4];
        red_add4(dst + c4*4, make_float4(v.x*w, v.y*w, v.z*w, v.w*w));
    }
    if (!lane) {
        atomicAdd(&g_cden[(size_t)b*NS + cell], w);
        g_wpt[p]   = w;
        out_idx[p] = (float)cell;
    }
}

__global__ void k_xdown(float* __restrict__ out_xd) {
    int row  = blockIdx.x*8 + (threadIdx.x>>5);
    int lane = threadIdx.x & 31;
    float rcp = 1.f/(g_cden[row] + EPSV);
    const float4* src = (const float4*)(g_cnum + (size_t)row*COUT);
    float4* dst = (float4*)(out_xd + (size_t)row*COUT);
    #pragma unroll
    for (int q = 0; q < 2; q++) {
        int c4 = q*32 + lane;
        float4 v = src[c4];
        dst[c4] = make_float4(fmaxf(v.x*rcp,0.f), fmaxf(v.y*rcp,0.f),
                              fmaxf(v.z*rcp,0.f), fmaxf(v.w*rcp,0.f));
    }
}

__global__ void k_aggmax(const float* __restrict__ loc, const float* __restrict__ aggw) {
    __shared__ float sm[256];
    int p = blockIdx.x*256 + threadIdx.x;
    int b = p >> 16;
    int cell = grid_cell(loc[2*p], loc[2*p+1], HC, WC);
    float aw = aggw[p] * g_wpt[p] / (g_cden[(size_t)b*NS + cell] + EPSV);
    g_wpt[p] = aw;
    sm[threadIdx.x] = aw;
    __syncthreads();
    for (int s = 128; s; s >>= 1) {
        if (threadIdx.x < s) sm[threadIdx.x] = fmaxf(sm[threadIdx.x], sm[threadIdx.x+s]);
        __syncthreads();
    }
    if (!threadIdx.x) atomicMax(&g_maxw[b], __float_as_uint(sm[0]));
}

__global__ void k_aggnorm(float* __restrict__ out_aw) {
    int p = blockIdx.x*256 + threadIdx.x;
    int b = p >> 16;
    out_aw[p] = g_wpt[p] / __uint_as_float(g_maxw[b]);
}

// ---------------- launch ----------------
extern "C" void kernel_launch(void* const* d_in, const int* in_sizes, int n_in,
                              void* d_out, int out_size) {
    const float* x      = (const float*)d_in[0];
    const float* loc    = (const float*)d_in[1];
    const int*   idxa   = (const int*)  d_in[2];
    const float* aggw   = (const float*)d_in[3];
    const float* conv_w = (const float*)d_in[4];
    const float* conv_b = (const float*)d_in[5];
    const float* skip_w = (const float*)d_in[6];
    const float* gamma  = (const float*)d_in[7];
    const float* beta   = (const float*)d_in[8];
    const float* conf_w = (const float*)d_in[9];
    const float* conf_b = (const float*)d_in[10];

    float* out      = (float*)d_out;
    float* out_xd   = out;                                    // [4,4096,256]
    float* out_xout = out + (size_t)BB*NS*COUT;               // [4,16384,256]
    float* out_conf = out_xout + (size_t)BB*NN*COUT;          // [4,16384,1]
    float* out_aw   = out_conf + (size_t)BB*NN;               // [4,65536,1]
    float* out_idx  = out_aw   + (size_t)BB*NP;               // [4,65536]

    cudaFuncSetAttribute(k_conv, cudaFuncAttributeMaxDynamicSharedMemorySize, CV_SMEM);

    k_init<<<2048, 256>>>(skip_w, conv_w);
    k_token2map<<<BB*NP/8, 256>>>(x, loc, idxa);
    k_norm<<<(BB*HH*WW*CIN/4)/256, 256>>>();
    k_conv<<<dim3(HD, BB), 256, CV_SMEM>>>(conv_b);
    k_map2token<<<BB*NP/8, 256>>>(loc, idxa, aggw);
    k_skip<<<dim3(BB*NN/64, COUT/64), 256>>>(x);
    k_bnstats<<<BB*NN/256, 256>>>();
    k_bnfinal<<<1, 256>>>(gamma, beta);
    k_bnconf<<<BB*NN/8, 256>>>(conf_w, conf_b, out_xout, out_conf);
    k_cluster<<<BB*NP/8, 256>>>(loc, idxa, out_idx);
    k_xdown<<<BB*NS/8, 256>>>(out_xd);
    k_aggmax<<<BB*NP/256, 256>>>(loc, aggw);
    k_aggnorm<<<BB*NP/256, 256>>>(out_aw);
}

// round 7
// speedup vs baseline: 1.7312x; 1.0550x over previous
#include <cuda_runtime.h>
#include <math.h>
#include <stdint.h>

#define BB   4
#define NN   16384
#define CIN  128
#define COUT 256
#define HH   256
#define WW   256
#define NP   65536      // N0 = H*W points
#define HD   128
#define WD   128
#define HC   64
#define WC   64
#define NS   4096       // HC*WC
#define EPSV 1e-6f
#define KTOT 1152       // 9*CIN
#define SLABS 36        // KTOT/32

// ---------------- scratch (device globals: no allocation allowed) ----------------
__device__ float  g_ssum[(size_t)BB*HH*WW*CIN];   // token2map sum -> normalized tf32 map (128MB)
__device__ float  g_cnt [(size_t)BB*HH*WW];       // token2map count
__device__ float  g_y   [(size_t)BB*HD*WD*COUT];  // conv output        (64MB)
__device__ float  g_num [(size_t)BB*NN*COUT];     // map2token num -> tok (64MB)
__device__ float  g_den [(size_t)BB*NN];
__device__ float  g_tokn[(size_t)BB*NN*COUT];     // BN-normalized tokens (64MB)
__device__ float  g_wexp[(size_t)BB*NN];          // exp(conf)
__device__ double g_bnsum[COUT];
__device__ double g_bnsq [COUT];
__device__ float  g_scale[COUT];
__device__ float  g_shift[COUT];
__device__ float  g_cnum[(size_t)BB*NS*COUT];     // cluster num (16MB)
__device__ float  g_cden[(size_t)BB*NS];
__device__ float  g_wpt [(size_t)BB*NP];          // per-point weight, reused
__device__ unsigned g_maxw[BB];
__device__ float  g_wT  [CIN*COUT];               // skip_w transposed [k][n]
__device__ float4 g_wBp [(size_t)SLABS*2048];     // conv weights, pre-swizzled smem image per slab

// ---------------- helpers ----------------
__device__ __forceinline__ void red_add4(float* p, float4 v) {
    asm volatile("red.global.add.v4.f32 [%0], {%1,%2,%3,%4};"
                 :: "l"(__cvta_generic_to_global(p)),
                    "f"(v.x), "f"(v.y), "f"(v.z), "f"(v.w) : "memory");
}

__device__ __forceinline__ int grid_cell(float lx, float ly, int Hg, int Wg) {
    lx = fminf(fmaxf(lx, -1.f), 1.f);
    ly = fminf(fmaxf(ly, -1.f), 1.f);
    int px = min(max(__float2int_rn(0.5f*(lx+1.f)*(float)Wg - 0.5f), 0), Wg-1);
    int py = min(max(__float2int_rn(0.5f*(ly+1.f)*(float)Hg - 0.5f), 0), Hg-1);
    return py*Wg + px;
}

__device__ __forceinline__ float to_tf32(float x) {
    uint32_t u; asm("cvt.rna.tf32.f32 %0, %1;" : "=r"(u) : "f"(x));
    return __uint_as_float(u);
}
__device__ __forceinline__ float4 tf4(float4 v) {
    return make_float4(to_tf32(v.x), to_tf32(v.y), to_tf32(v.z), to_tf32(v.w));
}

__device__ __forceinline__ uint32_t smem_u32(const void* p) {
    uint32_t a;
    asm("{ .reg .u64 t; cvta.to.shared.u64 t, %1; cvt.u32.u64 %0, t; }" : "=r"(a) : "l"(p));
    return a;
}

__device__ __forceinline__ void cpa16(uint32_t dst, const float* src, int srcsz) {
    asm volatile("cp.async.cg.shared.global [%0], [%1], 16, %2;"
                 :: "r"(dst), "l"(__cvta_generic_to_global(src)), "r"(srcsz) : "memory");
}

__device__ __forceinline__ void mma8(float& d0, float& d1, float& d2, float& d3,
                                     float a0, float a1, float a2, float a3,
                                     float b0, float b1) {
    asm volatile("mma.sync.aligned.m16n8k8.row.col.f32.tf32.tf32.f32 "
                 "{%0,%1,%2,%3},{%4,%5,%6,%7},{%8,%9},{%0,%1,%2,%3};"
                 : "+f"(d0), "+f"(d1), "+f"(d2), "+f"(d3)
                 : "r"(__float_as_uint(a0)), "r"(__float_as_uint(a1)),
                   "r"(__float_as_uint(a2)), "r"(__float_as_uint(a3)),
                   "r"(__float_as_uint(b0)), "r"(__float_as_uint(b1)));
}

// ---------------- kernels ----------------
// fused: zero all accumulators + transpose skip_w + build pre-swizzled conv-B image
__global__ void k_init(const float* __restrict__ skw, const float* __restrict__ cw) {
    size_t t = (size_t)blockIdx.x*blockDim.x + threadIdx.x;
    size_t stride = (size_t)gridDim.x*blockDim.x;
    float4 z = make_float4(0.f,0.f,0.f,0.f);
    for (size_t i=t; i < (size_t)BB*HH*WW*CIN/4; i+=stride) ((float4*)g_ssum)[i]=z;
    for (size_t i=t; i < (size_t)BB*HH*WW/4;     i+=stride) ((float4*)g_cnt )[i]=z;
    for (size_t i=t; i < (size_t)BB*NN*COUT/4;   i+=stride) ((float4*)g_num )[i]=z;
    for (size_t i=t; i < (size_t)BB*NN/4;        i+=stride) ((float4*)g_den )[i]=z;
    for (size_t i=t; i < (size_t)BB*NS*COUT/4;   i+=stride) ((float4*)g_cnum)[i]=z;
    for (size_t i=t; i < (size_t)BB*NS/4;        i+=stride) ((float4*)g_cden)[i]=z;
    if (t < COUT) { g_bnsum[t]=0.0; g_bnsq[t]=0.0; }
    if (t < BB)   g_maxw[t]=0u;
    if (t < CIN*COUT)
        g_wT[t] = skw[((int)t % COUT)*CIN + ((int)t / COUT)];
    if (t < (size_t)SLABS*2048) {
        int fi = (int)t;
        int s  = fi >> 11, r = fi & 2047;
        int nt = r >> 6, h2 = (r >> 5) & 1, g = (r >> 2) & 7, c = r & 3;
        int n  = nt*8 + g;
        int k0 = s*32 + h2*16 + c;
        float4 v = make_float4(cw[(size_t)k0*COUT + n],      cw[(size_t)(k0+4)*COUT + n],
                               cw[(size_t)(k0+8)*COUT + n],  cw[(size_t)(k0+12)*COUT + n]);
        g_wBp[fi] = tf4(v);
    }
}

// scatter token features to H x W map (sum + count)
__global__ void k_token2map(const float* __restrict__ x, const float* __restrict__ loc,
                            const int* __restrict__ idx_agg) {
    int p    = blockIdx.x*8 + (threadIdx.x>>5);
    int lane = threadIdx.x & 31;
    int b    = p >> 16;
    float lx = loc[2*p], ly = loc[2*p+1];
    int cell = grid_cell(lx, ly, HH, WW);
    int i    = idx_agg[p];
    const float4* src = (const float4*)(x + ((size_t)b*NN + i)*CIN);
    float* dst = g_ssum + ((size_t)b*HH*WW + cell)*CIN;
    float4 v = src[lane];
    red_add4(dst + lane*4, v);
    if (!lane) atomicAdd(&g_cnt[(size_t)b*HH*WW + cell], 1.0f);
}

// normalize map in place AND round to tf32: ssum = tf32(ssum / (cnt + eps))
__global__ void k_norm() {
    size_t i = (size_t)blockIdx.x*256 + threadIdx.x;
    float rcp = 1.f/(g_cnt[i >> 5] + EPSV);
    float4 v = ((float4*)g_ssum)[i];
    v.x*=rcp; v.y*=rcp; v.z*=rcp; v.w*=rcp;
    ((float4*)g_ssum)[i] = tf4(v);
}

// ---- 3x3 stride-2 conv as implicit GEMM on mma.sync TF32, 3-stage cp.async pipeline ----
// CTA: oy=blockIdx.x, b=blockIdx.y. 512 threads / 16 warps, warp tile 32m x 64n.
// M=128 pixels (ox), N=256 couts, K=1152 = 36 x K32.
#define CV_BUF   49152
#define CV_A(i)  ((i)*CV_BUF)
#define CV_B(i)  ((i)*CV_BUF + 16384)
#define CV_BIAS  (3*CV_BUF)
#define CV_SMEM  (CV_BIAS + 1024)

__device__ __forceinline__ void cv_stage(uint32_t sb, int s, int buf,
                                         int oy, const float* __restrict__ xin, int tid) {
    int tap = s >> 2, cinb = (s & 3) * 32;
    int ky = tap / 3, kx = tap - 3*ky;
    int iy = 2*oy - 1 + ky;
    bool iyok = (unsigned)iy < HH;
    int r = tid >> 2, q0 = (tid & 3) * 2;        // 512 threads: 2 A-chunks each
    int ix = 2*r - 1 + kx;
    bool ok = iyok && ((unsigned)ix < WW);
    const float* src = xin + ((size_t)(iyok ? iy : 0)*WW + (ok ? ix : 0))*CIN + cinb;
    uint32_t dstA = sb + CV_A(buf) + r*128;
    int sz = ok ? 16 : 0;
    int sw = r & 7;
    #pragma unroll
    for (int j = 0; j < 2; j++) {
        int q = q0 + j;
        cpa16(dstA + ((q ^ sw) * 16), src + q*4, sz);
    }
    const float4* bsrc = g_wBp + (size_t)s*2048 + tid*4;   // 4 B-chunks each
    uint32_t dstB = sb + CV_B(buf) + tid*64;
    #pragma unroll
    for (int j = 0; j < 4; j++)
        cpa16(dstB + j*16, (const float*)(bsrc + j), 16);
    asm volatile("cp.async.commit_group;" ::: "memory");
}

__device__ __forceinline__ float ldsA(const float* sA, int r, int k) {
    int kk = ((((k >> 2) ^ (r & 7)) << 2) | (k & 3));
    return sA[r*32 + kk];
}

__global__ void __launch_bounds__(512, 1) k_conv(const float* __restrict__ cb) {
    extern __shared__ char smem[];
    uint32_t sb = smem_u32(smem);
    int tid = threadIdx.x, w = tid >> 5, lane = tid & 31;
    int g = lane >> 2, cl = lane & 3;
    int wm = w & 3, wn = w >> 2;                 // warp tile 32m x 64n
    int oy = blockIdx.x, b = blockIdx.y;
    const float* xin = g_ssum + (size_t)b*HH*WW*CIN;

    if (tid < 256) *(float*)(smem + CV_BIAS + tid*4) = cb[tid];

    float acc[2][8][4];
    #pragma unroll
    for (int mt=0;mt<2;mt++) for (int nt=0;nt<8;nt++) for (int r2=0;r2<4;r2++) acc[mt][nt][r2]=0.f;

    cv_stage(sb, 0, 0, oy, xin, tid);
    cv_stage(sb, 1, 1, oy, xin, tid);

    int bufc = 0;                                  // buffer of slab s
    for (int s = 0; s < SLABS; s++) {
        if (s < SLABS-1) asm volatile("cp.async.wait_group 1;" ::: "memory");
        else             asm volatile("cp.async.wait_group 0;" ::: "memory");
        __syncthreads();
        int bufn = bufc + 2; if (bufn >= 3) bufn -= 3;
        if (s + 2 < SLABS) cv_stage(sb, s + 2, bufn, oy, xin, tid);
        const float*  sA = (const float*) (smem + CV_A(bufc));
        const float4* sB = (const float4*)(smem + CV_B(bufc));
        #pragma unroll
        for (int h2 = 0; h2 < 2; h2++) {
            float4 bv[8];
            #pragma unroll
            for (int nt = 0; nt < 8; nt++)
                bv[nt] = sB[(wn*8 + nt)*64 + h2*32 + g*4 + cl];
            #pragma unroll
            for (int hh = 0; hh < 2; hh++) {
                int kc = (h2*2 + hh)*8 + cl;
                float a[2][4];
                #pragma unroll
                for (int mt = 0; mt < 2; mt++) {
                    int r0 = wm*32 + mt*16 + g;
                    a[mt][0] = ldsA(sA, r0,     kc);
                    a[mt][1] = ldsA(sA, r0 + 8, kc);
                    a[mt][2] = ldsA(sA, r0,     kc + 4);
                    a[mt][3] = ldsA(sA, r0 + 8, kc + 4);
                }
                #pragma unroll
                for (int mt = 0; mt < 2; mt++)
                    #pragma unroll
                    for (int nt = 0; nt < 8; nt++) {
                        float b0 = hh ? bv[nt].z : bv[nt].x;
                        float b1 = hh ? bv[nt].w : bv[nt].y;
                        mma8(acc[mt][nt][0], acc[mt][nt][1], acc[mt][nt][2], acc[mt][nt][3],
                             a[mt][0], a[mt][1], a[mt][2], a[mt][3], b0, b1);
                    }
            }
        }
        bufc++; if (bufc >= 3) bufc = 0;
    }

    // epilogue: D frag (m16n8): d0,d1 @ (g, 2c+{0,1}); d2,d3 @ (g+8, 2c+{0,1})
    const float* bias = (const float*)(smem + CV_BIAS);
    float* ybase = g_y + (((size_t)b*HD + oy)*WD)*COUT;
    #pragma unroll
    for (int mt = 0; mt < 2; mt++) {
        int ox0 = wm*32 + mt*16 + g;
        #pragma unroll
        for (int nt = 0; nt < 8; nt++) {
            int n = wn*64 + nt*8 + cl*2;
            float b0 = bias[n], b1 = bias[n+1];
            *(float2*)(ybase + (size_t)ox0*COUT + n)     = make_float2(acc[mt][nt][0]+b0, acc[mt][nt][1]+b1);
            *(float2*)(ybase + (size_t)(ox0+8)*COUT + n) = make_float2(acc[mt][nt][2]+b0, acc[mt][nt][3]+b1);
        }
    }
}

// bilinear gather from conv map at orig points, weighted scatter to tokens
__global__ void k_map2token(const float* __restrict__ loc, const int* __restrict__ idx_agg,
                            const float* __restrict__ aggw) {
    int p    = blockIdx.x*8 + (threadIdx.x>>5);
    int lane = threadIdx.x & 31;
    int b    = p >> 16;
    float lx = fminf(fmaxf(loc[2*p],   -1.f), 1.f);
    float ly = fminf(fmaxf(loc[2*p+1], -1.f), 1.f);
    float fx = fminf(fmaxf(0.5f*(lx+1.f)*(float)WD - 0.5f, 0.f), (float)(WD-1));
    float fy = fminf(fmaxf(0.5f*(ly+1.f)*(float)HD - 0.5f, 0.f), (float)(HD-1));
    float x0f = floorf(fx), y0f = floorf(fy);
    float wx = fx - x0f, wy = fy - y0f;
    int x0 = (int)x0f, y0 = (int)y0f;
    int x1 = min(x0+1, WD-1), y1 = min(y0+1, HD-1);
    const float* base = g_y + (size_t)b*HD*WD*COUT;
    const float4* r00 = (const float4*)(base + (size_t)(y0*WD+x0)*COUT);
    const float4* r01 = (const float4*)(base + (size_t)(y0*WD+x1)*COUT);
    const float4* r10 = (const float4*)(base + (size_t)(y1*WD+x0)*COUT);
    const float4* r11 = (const float4*)(base + (size_t)(y1*WD+x1)*COUT);
    float w00=(1.f-wx)*(1.f-wy), w01=wx*(1.f-wy), w10=(1.f-wx)*wy, w11=wx*wy;
    float wpt = aggw[p];
    int i = idx_agg[p];
    float* dst = g_num + ((size_t)b*NN + i)*COUT;
    #pragma unroll
    for (int q = 0; q < 2; q++) {
        int c4 = q*32 + lane;
        float4 a = r00[c4], bq = r01[c4], cc = r10[c4], d = r11[c4];
        float4 f;
        f.x = (w00*a.x + w01*bq.x + w10*cc.x + w11*d.x)*wpt;
        f.y = (w00*a.y + w01*bq.y + w10*cc.y + w11*d.y)*wpt;
        f.z = (w00*a.z + w01*bq.z + w10*cc.z + w11*d.z)*wpt;
        f.w = (w00*a.w + w01*bq.w + w10*cc.w + w11*d.w)*wpt;
        red_add4(dst + c4*4, f);
    }
    if (!lane) atomicAdd(&g_den[(size_t)b*NN + i], wpt);
}

// skip GEMM (x @ skip_w^T) fused with tok = num/(den+eps) + skip -> overwrite g_num
__global__ void __launch_bounds__(256) k_skip(const float* __restrict__ x) {
    __shared__ __align__(16) float As2[16][68];
    __shared__ __align__(16) float Bs2[16][64];
    int m0 = blockIdx.x*64, n0 = blockIdx.y*64;
    int tid = threadIdx.x;
    int tx = tid & 15, ty = tid >> 4;
    int m_l = tid >> 2, kq = (tid & 3)*4;
    int kb  = tid >> 4, nb = (tid & 15)*4;
    float acc[4][4] = {};
    const float* arow = x + (size_t)(m0 + m_l)*CIN;
    for (int cc = 0; cc < 8; cc++) {
        float4 va = *(const float4*)(arow + cc*16 + kq);
        __syncthreads();
        As2[kq+0][m_l]=va.x; As2[kq+1][m_l]=va.y; As2[kq+2][m_l]=va.z; As2[kq+3][m_l]=va.w;
        *(float4*)&Bs2[kb][nb] = *(const float4*)(g_wT + (size_t)(cc*16+kb)*COUT + n0 + nb);
        __syncthreads();
        #pragma unroll
        for (int k = 0; k < 16; k++) {
            float4 a  = *(float4*)&As2[k][ty*4];
            float4 bv = *(float4*)&Bs2[k][tx*4];
            acc[0][0]+=a.x*bv.x; acc[0][1]+=a.x*bv.y; acc[0][2]+=a.x*bv.z; acc[0][3]+=a.x*bv.w;
            acc[1][0]+=a.y*bv.x; acc[1][1]+=a.y*bv.y; acc[1][2]+=a.y*bv.z; acc[1][3]+=a.y*bv.w;
            acc[2][0]+=a.z*bv.x; acc[2][1]+=a.z*bv.y; acc[2][2]+=a.z*bv.z; acc[2][3]+=a.z*bv.w;
            acc[3][0]+=a.w*bv.x; acc[3][1]+=a.w*bv.y; acc[3][2]+=a.w*bv.z; acc[3][3]+=a.w*bv.w;
        }
    }
    #pragma unroll
    for (int i2 = 0; i2 < 4; i2++) {
        int row = m0 + ty*4 + i2;
        float rcp = 1.f/(g_den[row] + EPSV);
        float* orow = g_num + (size_t)row*COUT + n0 + tx*4;
        float4 nv = *(float4*)orow;
        float4 o = make_float4(acc[i2][0] + nv.x*rcp, acc[i2][1] + nv.y*rcp,
                               acc[i2][2] + nv.z*rcp, acc[i2][3] + nv.w*rcp);
        *(float4*)orow = o;
    }
}

__global__ void k_bnstats() {
    int c  = threadIdx.x;
    int r0 = blockIdx.x*256;
    double s = 0.0, s2 = 0.0;
    for (int r = 0; r < 256; r++) {
        float v = g_num[(size_t)(r0 + r)*COUT + c];
        s += v; s2 += (double)v*v;
    }
    atomicAdd(&g_bnsum[c], s);
    atomicAdd(&g_bnsq[c],  s2);
}

__global__ void k_bnfinal(const float* __restrict__ gam, const float* __restrict__ bet) {
    int c = threadIdx.x;
    double m  = (double)BB*NN;
    double mu = g_bnsum[c]/m;
    double var = g_bnsq[c]/m - mu*mu;
    float sc = gam[c] * (float)(1.0/sqrt(var + 1e-5));
    g_scale[c] = sc;
    g_shift[c] = bet[c] - (float)mu*sc;
}

__global__ void k_bnconf(const float* __restrict__ cw, const float* __restrict__ cbv,
                         float* __restrict__ out_xout, float* __restrict__ out_conf) {
    int row  = blockIdx.x*8 + (threadIdx.x>>5);
    int lane = threadIdx.x & 31;
    const float4* t  = (const float4*)(g_num  + (size_t)row*COUT);
    float4* tn       = (float4*)(g_tokn + (size_t)row*COUT);
    float4* xo       = (float4*)(out_xout + (size_t)row*COUT);
    float dot = 0.f;
    #pragma unroll
    for (int q = 0; q < 2; q++) {
        int c4 = q*32 + lane;
        float4 v  = t[c4];
        float4 sc = ((const float4*)g_scale)[c4];
        float4 sh = ((const float4*)g_shift)[c4];
        float4 w  = ((const float4*)cw)[c4];
        float4 r = make_float4(v.x*sc.x+sh.x, v.y*sc.y+sh.y, v.z*sc.z+sh.z, v.w*sc.w+sh.w);
        dot += r.x*w.x + r.y*w.y + r.z*w.z + r.w*w.w;
        tn[c4] = r;
        xo[c4] = make_float4(fmaxf(r.x,0.f), fmaxf(r.y,0.f), fmaxf(r.z,0.f), fmaxf(r.w,0.f));
    }
    #pragma unroll
    for (int o = 16; o; o >>= 1) dot += __shfl_xor_sync(0xffffffffu, dot, o);
    if (!lane) {
        float cf = dot + cbv[0];
        out_conf[row] = cf;
        g_wexp[row]   = expf(cf);
    }
}

__global__ void k_cluster(const float* __restrict__ loc, const int* __restrict__ idx_agg,
                          float* __restrict__ out_idx) {
    int p    = blockIdx.x*8 + (threadIdx.x>>5);
    int lane = threadIdx.x & 31;
    int b    = p >> 16;
    int cell = grid_cell(loc[2*p], loc[2*p+1], HC, WC);
    int i    = idx_agg[p];
    float w  = g_wexp[(size_t)b*NN + i];
    const float4* src = (const float4*)(g_tokn + ((size_t)b*NN + i)*COUT);
    float* dst = g_cnum + ((size_t)b*NS + cell)*COUT;
    #pragma unroll
    for (int q = 0; q < 2; q++) {
        int c4 = q*32 + lane;
        float4 v = src[c4];
        red_add4(dst + c4*4, make_float4(v.x*w, v.y*w, v.z*w, v.w*w));
    }
    if (!lane) {
        atomicAdd(&g_cden[(size_t)b*NS + cell], w);
        g_wpt[p]   = w;
        out_idx[p] = (float)cell;
    }
}

__global__ void k_xdown(float* __restrict__ out_xd) {
    int row  = blockIdx.x*8 + (threadIdx.x>>5);
    int lane = threadIdx.x & 31;
    float rcp = 1.f/(g_cden[row] + EPSV);
    const float4* src = (const float4*)(g_cnum + (size_t)row*COUT);
    float4* dst = (float4*)(out_xd + (size_t)row*COUT);
    #pragma unroll
    for (int q = 0; q < 2; q++) {
        int c4 = q*32 + lane;
        float4 v = src[c4];
        dst[c4] = make_float4(fmaxf(v.x*rcp,0.f), fmaxf(v.y*rcp,0.f),
                              fmaxf(v.z*rcp,0.f), fmaxf(v.w*rcp,0.f));
    }
}

__global__ void k_aggmax(const float* __restrict__ loc, const float* __restrict__ aggw) {
    __shared__ float sm[256];
    int p = blockIdx.x*256 + threadIdx.x;
    int b = p >> 16;
    int cell = grid_cell(loc[2*p], loc[2*p+1], HC, WC);
    float aw = aggw[p] * g_wpt[p] / (g_cden[(size_t)b*NS + cell] + EPSV);
    g_wpt[p] = aw;
    sm[threadIdx.x] = aw;
    __syncthreads();
    for (int s = 128; s; s >>= 1) {
        if (threadIdx.x < s) sm[threadIdx.x] = fmaxf(sm[threadIdx.x], sm[threadIdx.x+s]);
        __syncthreads();
    }
    if (!threadIdx.x) atomicMax(&g_maxw[b], __float_as_uint(sm[0]));
}

__global__ void k_aggnorm(float* __restrict__ out_aw) {
    int p = blockIdx.x*256 + threadIdx.x;
    int b = p >> 16;
    out_aw[p] = g_wpt[p] / __uint_as_float(g_maxw[b]);
}

// ---------------- launch ----------------
extern "C" void kernel_launch(void* const* d_in, const int* in_sizes, int n_in,
                              void* d_out, int out_size) {
    const float* x      = (const float*)d_in[0];
    const float* loc    = (const float*)d_in[1];
    const int*   idxa   = (const int*)  d_in[2];
    const float* aggw   = (const float*)d_in[3];
    const float* conv_w = (const float*)d_in[4];
    const float* conv_b = (const float*)d_in[5];
    const float* skip_w = (const float*)d_in[6];
    const float* gamma  = (const float*)d_in[7];
    const float* beta   = (const float*)d_in[8];
    const float* conf_w = (const float*)d_in[9];
    const float* conf_b = (const float*)d_in[10];

    float* out      = (float*)d_out;
    float* out_xd   = out;                                    // [4,4096,256]
    float* out_xout = out + (size_t)BB*NS*COUT;               // [4,16384,256]
    float* out_conf = out_xout + (size_t)BB*NN*COUT;          // [4,16384,1]
    float* out_aw   = out_conf + (size_t)BB*NN;               // [4,65536,1]
    float* out_idx  = out_aw   + (size_t)BB*NP;               // [4,65536]

    cudaFuncSetAttribute(k_conv, cudaFuncAttributeMaxDynamicSharedMemorySize, CV_SMEM);

    k_init<<<2048, 256>>>(skip_w, conv_w);
    k_token2map<<<BB*NP/8, 256>>>(x, loc, idxa);
    k_norm<<<(BB*HH*WW*CIN/4)/256, 256>>>();
    k_conv<<<dim3(HD, BB), 512, CV_SMEM>>>(conv_b);
    k_map2token<<<BB*NP/8, 256>>>(loc, idxa, aggw);
    k_skip<<<dim3(BB*NN/64, COUT/64), 256>>>(x);
    k_bnstats<<<BB*NN/256, 256>>>();
    k_bnfinal<<<1, 256>>>(gamma, beta);
    k_bnconf<<<BB*NN/8, 256>>>(conf_w, conf_b, out_xout, out_conf);
    k_cluster<<<BB*NP/8, 256>>>(loc, idxa, out_idx);
    k_xdown<<<BB*NS/8, 256>>>(out_xd);
    k_aggmax<<<BB*NP/256, 256>>>(loc, aggw);
    k_aggnorm<<<BB*NP/256, 256>>>(out_aw);
}